// round 2
// baseline (speedup 1.0000x reference)
#include <cuda_runtime.h>
#include <cub/cub.cuh>
#include <cstdint>
#include <math.h>

// ---------------- problem constants ----------------
#define NBATCH 4
#define FH 50
#define FW 50
#define CIN 512
#define COUT 512
#define NA 22500          // anchors per batch (50*50*9)
#define NPRE 3000
#define NPOST 300
#define NWORDS 94         // ceil(3000/32)

// output layout (flattened tuple, float32)
#define OFF_LOCS   0            // 4*22500*4 = 360000
#define OFF_SCORES 360000       // 4*22500*2 = 180000
#define OFF_ROIS   540000       // 4*300*4   = 4800
#define OFF_RIDX   544800       // 1200
#define OFF_ANCH   546000       // 22500*4   = 90000
// total 636000

// ---------------- device scratch ----------------
__device__ float g_feat[(size_t)NBATCH * 2500 * 512];   // NHWC feat
__device__ float g_wT[(size_t)512 * 9 * 512];            // [ci][tap][ko]
__device__ float g_hwT[(size_t)512 * 54];                // [k][c], c: 0..35 loc, 36..53 score
__device__ float g_boxes[(size_t)NBATCH * NA * 4];
__device__ unsigned g_keys[(size_t)NBATCH * NA];
__device__ unsigned g_keysOut[(size_t)NBATCH * NA];
__device__ int g_vals[(size_t)NBATCH * NA];
__device__ int g_valsOut[(size_t)NBATCH * NA];
__device__ float g_top[(size_t)NBATCH * NPRE * 4];
__device__ unsigned char g_topValid[(size_t)NBATCH * NPRE];
__device__ unsigned g_nmsMask[(size_t)NBATCH * NPRE * NWORDS];
__device__ int g_segOff[5] = {0, NA, 2 * NA, 3 * NA, 4 * NA};
__device__ unsigned char g_cubTemp[16 << 20];

// ---------------- weight transposes ----------------
__global__ void wtrans_kernel(const float* __restrict__ w) {
    int t = blockIdx.x * blockDim.x + threadIdx.x;
    if (t >= 512 * 9 * 512) return;
    int ko = t % 512;
    int tap = (t / 512) % 9;
    int ci = t / (512 * 9);
    g_wT[t] = w[((size_t)ko * 512 + ci) * 9 + tap];
}

__global__ void hwtrans_kernel(const float* __restrict__ loc_w,
                               const float* __restrict__ score_w) {
    int t = blockIdx.x * blockDim.x + threadIdx.x;
    if (t >= 512 * 54) return;
    int k = t / 54, c = t % 54;
    float v;
    if (c < 36) v = loc_w[(size_t)c * 512 + k];
    else        v = score_w[(size_t)(c - 36) * 512 + k];
    g_hwT[t] = v;
}

// ---------------- 3x3 conv + ReLU (implicit GEMM) ----------------
// block: 2 output rows x 50 x x 64 ko. threads 256:
//   sp = tid & 127 (spatial lane, active < 100: row = sp/50, xx = sp%50)
//   kg = tid >> 7  (0/1 -> 32 ko each)
#define CONV_CC 8
__global__ void __launch_bounds__(256) conv3x3_kernel(const float* __restrict__ x,
                                                      const float* __restrict__ bias) {
    __shared__ float sIn[CONV_CC][4][52];
    __shared__ float sW[CONV_CC][9][64];
    int ko0 = blockIdx.x * 64;
    int y0 = blockIdx.y * 2;
    int n = blockIdx.z;
    int tid = threadIdx.x;
    int sp = tid & 127;
    int kg = tid >> 7;
    int row = sp / 50, xx = sp % 50;
    bool active = sp < 100;

    float acc[32];
#pragma unroll
    for (int q = 0; q < 32; q++) acc[q] = 0.f;

    for (int c0 = 0; c0 < 512; c0 += CONV_CC) {
        __syncthreads();
        // input tile: rows y0-1 .. y0+2, cols -1..50, CONV_CC channels
        for (int t = tid; t < CONV_CC * 4 * 52; t += 256) {
            int ci = t / 208;
            int rem = t % 208;
            int r = rem / 52;
            int col = rem % 52;
            int gy = y0 - 1 + r;
            int gx = col - 1;
            float v = 0.f;
            if (gy >= 0 && gy < FH && gx >= 0 && gx < FW)
                v = x[(((size_t)n * 512 + c0 + ci) * FH + gy) * FW + gx];
            sIn[ci][r][col] = v;
        }
        // weight tile: [ci][tap][64 ko]
        for (int t = tid; t < CONV_CC * 9 * 64; t += 256) {
            int ci = t / 576;
            int rem = t % 576;
            int tap = rem / 64;
            int ko = rem % 64;
            sW[ci][tap][ko] = g_wT[((size_t)(c0 + ci) * 9 + tap) * 512 + ko0 + ko];
        }
        __syncthreads();
        if (active) {
#pragma unroll 2
            for (int ci = 0; ci < CONV_CC; ci++) {
#pragma unroll
                for (int r = 0; r < 3; r++) {
#pragma unroll
                    for (int dx = 0; dx < 3; dx++) {
                        float a = sIn[ci][row + r][xx + dx];
                        const float4* wp =
                            reinterpret_cast<const float4*>(&sW[ci][r * 3 + dx][kg * 32]);
#pragma unroll
                        for (int q = 0; q < 8; q++) {
                            float4 w = wp[q];
                            acc[q * 4 + 0] += a * w.x;
                            acc[q * 4 + 1] += a * w.y;
                            acc[q * 4 + 2] += a * w.z;
                            acc[q * 4 + 3] += a * w.w;
                        }
                    }
                }
            }
        }
    }
    if (active) {
        size_t m = (size_t)n * 2500 + (size_t)(y0 + row) * 50 + xx;
        float4* outp = reinterpret_cast<float4*>(&g_feat[m * 512 + ko0 + kg * 32]);
#pragma unroll
        for (int q = 0; q < 8; q++) {
            int kb = ko0 + kg * 32 + q * 4;
            float4 v;
            v.x = fmaxf(acc[q * 4 + 0] + bias[kb + 0], 0.f);
            v.y = fmaxf(acc[q * 4 + 1] + bias[kb + 1], 0.f);
            v.z = fmaxf(acc[q * 4 + 2] + bias[kb + 2], 0.f);
            v.w = fmaxf(acc[q * 4 + 3] + bias[kb + 3], 0.f);
            outp[q] = v;
        }
    }
}

// ---------------- 1x1 heads (loc 36 + score 18) ----------------
__device__ __forceinline__ void write_head(float* out, int m, int c, float acc,
                                           const float* __restrict__ loc_b,
                                           const float* __restrict__ score_b) {
    int n = m / 2500, pos = m % 2500;
    if (c < 36) {
        int a = c >> 2, j = c & 3;
        out[(size_t)OFF_LOCS + ((size_t)n * NA + (size_t)pos * 9 + a) * 4 + j] = acc + loc_b[c];
    } else {
        int cc = c - 36;
        int a = cc >> 1, j = cc & 1;
        out[(size_t)OFF_SCORES + ((size_t)n * NA + (size_t)pos * 9 + a) * 2 + j] = acc + score_b[cc];
    }
}

__global__ void __launch_bounds__(256) heads_kernel(const float* __restrict__ loc_b,
                                                    const float* __restrict__ score_b,
                                                    float* out) {
    __shared__ float sf[16][512];
    int m0 = blockIdx.x * 16;
    int tid = threadIdx.x;
    for (int t = tid; t < 16 * 512; t += 256)
        sf[t >> 9][t & 511] = g_feat[((size_t)m0 << 9) + t];
    __syncthreads();
    int c = tid & 63;
    int mi = tid >> 6;  // 0..3
    if (c < 54) {
        float a0 = 0.f, a1 = 0.f, a2 = 0.f, a3 = 0.f;
#pragma unroll 4
        for (int k = 0; k < 512; k++) {
            float w = g_hwT[(size_t)k * 54 + c];
            a0 += sf[mi + 0][k] * w;
            a1 += sf[mi + 4][k] * w;
            a2 += sf[mi + 8][k] * w;
            a3 += sf[mi + 12][k] * w;
        }
        write_head(out, m0 + mi + 0, c, a0, loc_b, score_b);
        write_head(out, m0 + mi + 4, c, a1, loc_b, score_b);
        write_head(out, m0 + mi + 8, c, a2, loc_b, score_b);
        write_head(out, m0 + mi + 12, c, a3, loc_b, score_b);
    }
}

// ---------------- decode: anchors, loc2bbox, clip, valid, fg score ----------------
__global__ void decode_kernel(float* out, const int* __restrict__ imh,
                              const int* __restrict__ imw) {
    int t = blockIdx.x * blockDim.x + threadIdx.x;
    if (t >= NBATCH * NA) return;
    int b = t / NA, i = t % NA;
    int pos = i / 9, a = i % 9;
    int y = pos / 50, x = pos % 50;

    // base anchor (match numpy float64 math then cast to f32)
    int ri = a / 3, si = a % 3;
    double rr = (ri == 0) ? 0.5 : ((ri == 1) ? 1.0 : 2.0);
    double ss = (si == 0) ? 8.0 : ((si == 1) ? 16.0 : 32.0);
    double hh = 16.0 * ss * sqrt(rr);
    double wwd = 16.0 * ss * sqrt(1.0 / rr);
    float b0 = (float)(8.0 - wwd * 0.5);
    float b1 = (float)(8.0 - hh * 0.5);
    float b2 = (float)(8.0 + wwd * 0.5);
    float b3 = (float)(8.0 + hh * 0.5);
    float sx = (float)(x * 16), sy = (float)(y * 16);
    float ax1 = sx + b0, ay1 = sy + b1, ax2 = sx + b2, ay2 = sy + b3;

    if (b == 0) {
        float* ap = &out[(size_t)OFF_ANCH + (size_t)i * 4];
        ap[0] = ax1; ap[1] = ay1; ap[2] = ax2; ap[3] = ay2;
    }

    const float* lp = &out[(size_t)OFF_LOCS + ((size_t)b * NA + i) * 4];
    float l0 = lp[0], l1 = lp[1], l2 = lp[2], l3 = lp[3];
    const float* spt = &out[(size_t)OFF_SCORES + ((size_t)b * NA + i) * 2];
    float s0 = spt[0], s1 = spt[1];

    float aw = ax2 - ax1, ah = ay2 - ay1;
    float acx = ax1 + 0.5f * aw, acy = ay1 + 0.5f * ah;
    float cx = l0 * aw + acx, cy = l1 * ah + acy;
    float bw = expf(l2) * aw, bh = expf(l3) * ah;

    float Wf = (float)imw[0], Hf = (float)imh[0];
    float x1 = fminf(fmaxf(cx - 0.5f * bw, 0.f), Wf);
    float y1 = fminf(fmaxf(cy - 0.5f * bh, 0.f), Hf);
    float x2 = fminf(fmaxf(cx + 0.5f * bw, 0.f), Wf);
    float y2 = fminf(fmaxf(cy + 0.5f * bh, 0.f), Hf);

    bool valid = (x2 - x1 + 1.f >= 16.f) && (y2 - y1 + 1.f >= 16.f);

    float mx = fmaxf(s0, s1);
    float e0 = expf(s0 - mx), e1 = expf(s1 - mx);
    float fg = e1 / (e0 + e1);
    float score = valid ? fg : __int_as_float(0xff800000);  // -inf

    float* bp = &g_boxes[((size_t)b * NA + i) * 4];
    bp[0] = x1; bp[1] = y1; bp[2] = x2; bp[3] = y2;

    unsigned u = __float_as_uint(score);
    unsigned key = (u & 0x80000000u) ? ~u : (u | 0x80000000u);
    g_keys[(size_t)b * NA + i] = key;
    g_vals[(size_t)b * NA + i] = i;
}

// ---------------- gather top-3000 ----------------
__global__ void gather_kernel() {
    int t = blockIdx.x * blockDim.x + threadIdx.x;
    if (t >= NBATCH * NPRE) return;
    int b = t / NPRE, r = t % NPRE;
    unsigned key = g_keysOut[(size_t)b * NA + r];
    int i = g_valsOut[(size_t)b * NA + r];
    float4 box = reinterpret_cast<const float4*>(g_boxes)[(size_t)b * NA + i];
    reinterpret_cast<float4*>(g_top)[(size_t)b * NPRE + r] = box;
    g_topValid[(size_t)b * NPRE + r] = (key != 0x007FFFFFu) ? 1 : 0;  // key(-inf)=0x007FFFFF
}

// ---------------- IoU bitmask matrix ----------------
__global__ void __launch_bounds__(128) nms_mask_kernel() {
    __shared__ float4 sb[NPRE];
    int b = blockIdx.y;
    for (int t = threadIdx.x; t < NPRE; t += 128)
        sb[t] = reinterpret_cast<const float4*>(g_top)[(size_t)b * NPRE + t];
    __syncthreads();
    int i = blockIdx.x * 128 + threadIdx.x;
    if (i >= NPRE) return;
    float4 bi = sb[i];
    float ai = (bi.z - bi.x) * (bi.w - bi.y);
    unsigned* rowp = &g_nmsMask[((size_t)b * NPRE + i) * NWORDS];
    int jw0 = i >> 5;
    for (int jw = 0; jw < NWORDS; jw++) {
        unsigned bits = 0;
        if (jw >= jw0) {
            int jbase = jw * 32;
#pragma unroll 4
            for (int k = 0; k < 32; k++) {
                int j = jbase + k;
                if (j > i && j < NPRE) {
                    float4 bj = sb[j];
                    float iw = fmaxf(fminf(bi.z, bj.z) - fmaxf(bi.x, bj.x), 0.f);
                    float ih = fmaxf(fminf(bi.w, bj.w) - fmaxf(bi.y, bj.y), 0.f);
                    float inter = iw * ih;
                    float aj = (bj.z - bj.x) * (bj.w - bj.y);
                    float iou = inter / (ai + aj - inter + 1e-9f);
                    if (iou > 0.7f) bits |= 1u << k;
                }
            }
        }
        rowp[jw] = bits;
    }
}

// ---------------- serial greedy scan + emit rois ----------------
__global__ void __launch_bounds__(32) nms_scan_kernel(float* out) {
    __shared__ unsigned sup[96];
    __shared__ unsigned vbits[96];
    int b = blockIdx.x;
    int lane = threadIdx.x;

    // zero rois region for this batch
    for (int t = lane; t < NPOST * 4; t += 32)
        out[(size_t)OFF_ROIS + (size_t)b * NPOST * 4 + t] = 0.f;

#pragma unroll
    for (int q = 0; q < 3; q++) {
        int w = lane + 32 * q;
        sup[w] = 0;
        unsigned v = 0;
        if (w < NWORDS) {
            for (int k = 0; k < 32; k++) {
                int j = w * 32 + k;
                if (j < NPRE && g_topValid[(size_t)b * NPRE + j]) v |= 1u << k;
            }
        }
        vbits[w] = v;
    }
    __syncwarp();

    const unsigned* maskBase = &g_nmsMask[(size_t)b * NPRE * NWORDS];
    unsigned pre[4][3];
#pragma unroll
    for (int d = 0; d < 4; d++)
#pragma unroll
        for (int q = 0; q < 3; q++) {
            int w = lane + 32 * q;
            pre[d][q] = (w < NWORDS) ? maskBase[(size_t)d * NWORDS + w] : 0u;
        }
    __syncwarp();

    int cnt = 0;
    for (int i = 0; i < NPRE; i++) {
        int slot = i & 3;
        unsigned keep = 0;
        if (lane == 0) {
            unsigned sbit = (sup[i >> 5] >> (i & 31)) & 1u;
            unsigned vbit = (vbits[i >> 5] >> (i & 31)) & 1u;
            keep = vbit & (~sbit) & 1u;
        }
        keep = __shfl_sync(0xffffffffu, keep, 0);
        if (keep) {
#pragma unroll
            for (int q = 0; q < 3; q++) {
                int w = lane + 32 * q;
                if (w < NWORDS) sup[w] |= pre[slot][q];
            }
            if (lane < 4)
                out[(size_t)OFF_ROIS + ((size_t)b * NPOST + cnt) * 4 + lane] =
                    g_top[((size_t)b * NPRE + i) * 4 + lane];
            cnt++;
            if (cnt == NPOST) break;
        }
        int ip = i + 4;
#pragma unroll
        for (int q = 0; q < 3; q++) {
            int w = lane + 32 * q;
            pre[slot][q] = (ip < NPRE && w < NWORDS) ? maskBase[(size_t)ip * NWORDS + w] : 0u;
        }
        __syncwarp();
    }
}

// ---------------- roi indices ----------------
__global__ void ridx_kernel(float* out) {
    int t = blockIdx.x * blockDim.x + threadIdx.x;
    if (t < NBATCH * NPOST) out[(size_t)OFF_RIDX + t] = (float)(t / NPOST);
}

// ---------------- launch ----------------
extern "C" void kernel_launch(void* const* d_in, const int* in_sizes, int n_in,
                              void* d_out, int out_size) {
    const float* x = (const float*)d_in[0];
    const float* conv1_w = (const float*)d_in[1];
    const float* conv1_b = (const float*)d_in[2];
    const float* loc_w = (const float*)d_in[3];
    const float* loc_b = (const float*)d_in[4];
    const float* score_w = (const float*)d_in[5];
    const float* score_b = (const float*)d_in[6];
    const int* img_h = (const int*)d_in[7];
    const int* img_w = (const int*)d_in[8];
    float* out = (float*)d_out;

    wtrans_kernel<<<(512 * 9 * 512 + 255) / 256, 256>>>(conv1_w);
    hwtrans_kernel<<<(512 * 54 + 255) / 256, 256>>>(loc_w, score_w);

    conv3x3_kernel<<<dim3(8, 25, NBATCH), 256>>>(x, conv1_b);

    heads_kernel<<<625, 256>>>(loc_b, score_b, out);

    decode_kernel<<<(NBATCH * NA + 255) / 256, 256>>>(out, img_h, img_w);

    // stable descending sort per batch: key = flipped fg score, value = anchor idx
    void *pKeys, *pKeysOut, *pVals, *pValsOut, *pSeg, *pTemp;
    cudaGetSymbolAddress(&pKeys, g_keys);
    cudaGetSymbolAddress(&pKeysOut, g_keysOut);
    cudaGetSymbolAddress(&pVals, g_vals);
    cudaGetSymbolAddress(&pValsOut, g_valsOut);
    cudaGetSymbolAddress(&pSeg, g_segOff);
    cudaGetSymbolAddress(&pTemp, g_cubTemp);

    size_t temp_bytes = 0;
    cub::DeviceSegmentedRadixSort::SortPairsDescending(
        nullptr, temp_bytes, (const unsigned*)pKeys, (unsigned*)pKeysOut,
        (const int*)pVals, (int*)pValsOut, NBATCH * NA, NBATCH,
        (const int*)pSeg, ((const int*)pSeg) + 1, 0, 32, (cudaStream_t)0);
    if (temp_bytes <= (size_t)(16 << 20)) {
        cub::DeviceSegmentedRadixSort::SortPairsDescending(
            pTemp, temp_bytes, (const unsigned*)pKeys, (unsigned*)pKeysOut,
            (const int*)pVals, (int*)pValsOut, NBATCH * NA, NBATCH,
            (const int*)pSeg, ((const int*)pSeg) + 1, 0, 32, (cudaStream_t)0);
    }

    gather_kernel<<<(NBATCH * NPRE + 255) / 256, 256>>>();
    nms_mask_kernel<<<dim3((NPRE + 127) / 128, NBATCH), 128>>>();
    nms_scan_kernel<<<NBATCH, 32>>>(out);
    ridx_kernel<<<(NBATCH * NPOST + 255) / 256, 256>>>(out);
}

// round 3
// speedup vs baseline: 1.0492x; 1.0492x over previous
#include <cuda_runtime.h>
#include <cub/cub.cuh>
#include <cstdint>
#include <math.h>

// ---------------- problem constants ----------------
#define NBATCH 4
#define FH 50
#define FW 50
#define CIN 512
#define COUT 512
#define NA 22500          // anchors per batch (50*50*9)
#define NPRE 3000
#define NPOST 300
#define NWORDS 94         // ceil(3000/32)

// output layout (flattened tuple, float32)
#define OFF_LOCS   0            // 4*22500*4 = 360000
#define OFF_SCORES 360000       // 4*22500*2 = 180000
#define OFF_ROIS   540000       // 4*300*4   = 4800
#define OFF_RIDX   544800       // 1200
#define OFF_ANCH   546000       // 22500*4   = 90000
// total 636000

// ---------------- device scratch ----------------
__device__ float g_feat[(size_t)NBATCH * 2500 * 512];   // NHWC feat
__device__ float g_wT[(size_t)512 * 9 * 512];            // [ci][tap][ko]
__device__ float g_hwT[(size_t)512 * 54];                // [k][c], c: 0..35 loc, 36..53 score
__device__ float g_boxes[(size_t)NBATCH * NA * 4];
__device__ unsigned g_keys[(size_t)NBATCH * NA];
__device__ unsigned g_keysOut[(size_t)NBATCH * NA];
__device__ int g_vals[(size_t)NBATCH * NA];
__device__ int g_valsOut[(size_t)NBATCH * NA];
__device__ float g_top[(size_t)NBATCH * NPRE * 4];
__device__ unsigned char g_topValid[(size_t)NBATCH * NPRE];
__device__ unsigned g_nmsMask[(size_t)NBATCH * NPRE * NWORDS];
__device__ int g_segOff[5] = {0, NA, 2 * NA, 3 * NA, 4 * NA};
__device__ unsigned char g_cubTemp[16 << 20];

// ---------------- weight transposes ----------------
__global__ void wtrans_kernel(const float* __restrict__ w) {
    int t = blockIdx.x * blockDim.x + threadIdx.x;
    if (t >= 512 * 9 * 512) return;
    int ko = t % 512;
    int tap = (t / 512) % 9;
    int ci = t / (512 * 9);
    g_wT[t] = w[((size_t)ko * 512 + ci) * 9 + tap];
}

__global__ void hwtrans_kernel(const float* __restrict__ loc_w,
                               const float* __restrict__ score_w) {
    int t = blockIdx.x * blockDim.x + threadIdx.x;
    if (t >= 512 * 54) return;
    int k = t / 54, c = t % 54;
    float v;
    if (c < 36) v = loc_w[(size_t)c * 512 + k];
    else        v = score_w[(size_t)(c - 36) * 512 + k];
    g_hwT[t] = v;
}

// ---------------- 3x3 conv + ReLU, register-tiled implicit GEMM v2 ----------
// Block: 64 spatial (flattened within one image) x 256 ko. 256 threads.
// warp w (0..7)  -> spatial group of 8 positions  s0 + w*8 + j
// lane  l (0..31)-> 8 consecutive ko:  ko0 + l*8 .. +7
// Thread: 8 sp x 8 ko = 64 fp32 accumulators.
// smem: input halo tile [8ci][5rows][52cols] + weights [8ci][9tap][256ko]
#define CONV_SIN  (8 * 5 * 52)      // 2080 floats
#define CONV_SW   (8 * 9 * 256)     // 18432 floats
#define CONV_SMEM ((CONV_SIN + CONV_SW) * 4)

__global__ void __launch_bounds__(256, 2) conv3x3_v2(const float* __restrict__ x,
                                                     const float* __restrict__ bias) {
    extern __shared__ float sm[];
    float* sIn = sm;                 // [ci][r][c] : ci*260 + r*52 + c
    float* sW = sm + CONV_SIN;       // [ci][tap][ko]: (ci*9+tap)*256 + ko

    int mt = blockIdx.x;             // 0..39
    int nt = blockIdx.y;             // 0..1
    int n = blockIdx.z;              // 0..3
    int s0 = mt * 64;
    int y0 = s0 / 50;
    int ko0 = nt * 256;
    int tid = threadIdx.x;
    int wid = tid >> 5, lane = tid & 31;
    int koL = lane * 8;              // 0..248 within block N-tile

    int off[8], sglob[8];
#pragma unroll
    for (int j = 0; j < 8; j++) {
        int s = s0 + wid * 8 + j;
        int yy = s / 50, xx = s % 50;
        off[j] = (yy - y0 + 1) * 52 + xx + 1;   // row in [1,3], col in [1,50]
        sglob[j] = s;
    }

    float acc[8][8];
#pragma unroll
    for (int j = 0; j < 8; j++)
#pragma unroll
        for (int k = 0; k < 8; k++) acc[j][k] = 0.f;

    for (int c0 = 0; c0 < 512; c0 += 8) {
        __syncthreads();
        // input halo tile: rows y0-1 .. y0+3, cols -1..50
        for (int t = tid; t < CONV_SIN; t += 256) {
            int ci = t / 260;
            int rem = t % 260;
            int r = rem / 52;
            int cc = rem % 52;
            int gy = y0 - 1 + r;
            int gx = cc - 1;
            float v = 0.f;
            if (gy >= 0 && gy < FH && gx >= 0 && gx < FW)
                v = x[(((size_t)n * 512 + c0 + ci) * FH + gy) * FW + gx];
            sIn[t] = v;
        }
        // all 9 taps of weights for this ci-chunk
        for (int t = tid; t < CONV_SW; t += 256) {
            int ko = t & 255;
            int rest = t >> 8;
            int tap = rest % 9;
            int ci = rest / 9;
            sW[t] = g_wT[((size_t)(c0 + ci) * 9 + tap) * 512 + ko0 + ko];
        }
        __syncthreads();

#pragma unroll 1
        for (int ci = 0; ci < 8; ci++) {
            const float* sIci = &sIn[ci * 260];
            const float* sWci = &sW[ci * 9 * 256 + koL];
#pragma unroll
            for (int dy = 0; dy < 3; dy++) {
#pragma unroll
                for (int dx = 0; dx < 3; dx++) {
                    int tap = dy * 3 + dx;
                    float4 w0 = *reinterpret_cast<const float4*>(&sWci[tap * 256]);
                    float4 w1 = *reinterpret_cast<const float4*>(&sWci[tap * 256 + 4]);
                    int d = (dy - 1) * 52 + (dx - 1);
                    float a[8];
#pragma unroll
                    for (int j = 0; j < 8; j++) a[j] = sIci[off[j] + d];
#pragma unroll
                    for (int j = 0; j < 8; j++) {
                        acc[j][0] += a[j] * w0.x;
                        acc[j][1] += a[j] * w0.y;
                        acc[j][2] += a[j] * w0.z;
                        acc[j][3] += a[j] * w0.w;
                        acc[j][4] += a[j] * w1.x;
                        acc[j][5] += a[j] * w1.y;
                        acc[j][6] += a[j] * w1.z;
                        acc[j][7] += a[j] * w1.w;
                    }
                }
            }
        }
    }

    // epilogue: + bias, ReLU, store NHWC
    float4 b0 = *reinterpret_cast<const float4*>(&bias[ko0 + koL]);
    float4 b1 = *reinterpret_cast<const float4*>(&bias[ko0 + koL + 4]);
#pragma unroll
    for (int j = 0; j < 8; j++) {
        if (sglob[j] < 2500) {
            float4 v0, v1;
            v0.x = fmaxf(acc[j][0] + b0.x, 0.f);
            v0.y = fmaxf(acc[j][1] + b0.y, 0.f);
            v0.z = fmaxf(acc[j][2] + b0.z, 0.f);
            v0.w = fmaxf(acc[j][3] + b0.w, 0.f);
            v1.x = fmaxf(acc[j][4] + b1.x, 0.f);
            v1.y = fmaxf(acc[j][5] + b1.y, 0.f);
            v1.z = fmaxf(acc[j][6] + b1.z, 0.f);
            v1.w = fmaxf(acc[j][7] + b1.w, 0.f);
            float* op = &g_feat[((size_t)n * 2500 + sglob[j]) * 512 + ko0 + koL];
            *reinterpret_cast<float4*>(op) = v0;
            *reinterpret_cast<float4*>(op + 4) = v1;
        }
    }
}

// ---------------- 1x1 heads (loc 36 + score 18) ----------------
__device__ __forceinline__ void write_head(float* out, int m, int c, float acc,
                                           const float* __restrict__ loc_b,
                                           const float* __restrict__ score_b) {
    int n = m / 2500, pos = m % 2500;
    if (c < 36) {
        int a = c >> 2, j = c & 3;
        out[(size_t)OFF_LOCS + ((size_t)n * NA + (size_t)pos * 9 + a) * 4 + j] = acc + loc_b[c];
    } else {
        int cc = c - 36;
        int a = cc >> 1, j = cc & 1;
        out[(size_t)OFF_SCORES + ((size_t)n * NA + (size_t)pos * 9 + a) * 2 + j] = acc + score_b[cc];
    }
}

__global__ void __launch_bounds__(256) heads_kernel(const float* __restrict__ loc_b,
                                                    const float* __restrict__ score_b,
                                                    float* out) {
    __shared__ float sf[16][512];
    int m0 = blockIdx.x * 16;
    int tid = threadIdx.x;
    for (int t = tid; t < 16 * 512; t += 256)
        sf[t >> 9][t & 511] = g_feat[((size_t)m0 << 9) + t];
    __syncthreads();
    int c = tid & 63;
    int mi = tid >> 6;  // 0..3
    if (c < 54) {
        float a0 = 0.f, a1 = 0.f, a2 = 0.f, a3 = 0.f;
#pragma unroll 4
        for (int k = 0; k < 512; k++) {
            float w = g_hwT[(size_t)k * 54 + c];
            a0 += sf[mi + 0][k] * w;
            a1 += sf[mi + 4][k] * w;
            a2 += sf[mi + 8][k] * w;
            a3 += sf[mi + 12][k] * w;
        }
        write_head(out, m0 + mi + 0, c, a0, loc_b, score_b);
        write_head(out, m0 + mi + 4, c, a1, loc_b, score_b);
        write_head(out, m0 + mi + 8, c, a2, loc_b, score_b);
        write_head(out, m0 + mi + 12, c, a3, loc_b, score_b);
    }
}

// ---------------- decode: anchors, loc2bbox, clip, valid, fg score ----------------
__global__ void decode_kernel(float* out, const int* __restrict__ imh,
                              const int* __restrict__ imw) {
    int t = blockIdx.x * blockDim.x + threadIdx.x;
    if (t >= NBATCH * NA) return;
    int b = t / NA, i = t % NA;
    int pos = i / 9, a = i % 9;
    int y = pos / 50, x = pos % 50;

    int ri = a / 3, si = a % 3;
    double rr = (ri == 0) ? 0.5 : ((ri == 1) ? 1.0 : 2.0);
    double ss = (si == 0) ? 8.0 : ((si == 1) ? 16.0 : 32.0);
    double hh = 16.0 * ss * sqrt(rr);
    double wwd = 16.0 * ss * sqrt(1.0 / rr);
    float b0 = (float)(8.0 - wwd * 0.5);
    float b1 = (float)(8.0 - hh * 0.5);
    float b2 = (float)(8.0 + wwd * 0.5);
    float b3 = (float)(8.0 + hh * 0.5);
    float sx = (float)(x * 16), sy = (float)(y * 16);
    float ax1 = sx + b0, ay1 = sy + b1, ax2 = sx + b2, ay2 = sy + b3;

    if (b == 0) {
        float* ap = &out[(size_t)OFF_ANCH + (size_t)i * 4];
        ap[0] = ax1; ap[1] = ay1; ap[2] = ax2; ap[3] = ay2;
    }

    const float* lp = &out[(size_t)OFF_LOCS + ((size_t)b * NA + i) * 4];
    float l0 = lp[0], l1 = lp[1], l2 = lp[2], l3 = lp[3];
    const float* spt = &out[(size_t)OFF_SCORES + ((size_t)b * NA + i) * 2];
    float s0 = spt[0], s1 = spt[1];

    float aw = ax2 - ax1, ah = ay2 - ay1;
    float acx = ax1 + 0.5f * aw, acy = ay1 + 0.5f * ah;
    float cx = l0 * aw + acx, cy = l1 * ah + acy;
    float bw = expf(l2) * aw, bh = expf(l3) * ah;

    float Wf = (float)imw[0], Hf = (float)imh[0];
    float x1 = fminf(fmaxf(cx - 0.5f * bw, 0.f), Wf);
    float y1 = fminf(fmaxf(cy - 0.5f * bh, 0.f), Hf);
    float x2 = fminf(fmaxf(cx + 0.5f * bw, 0.f), Wf);
    float y2 = fminf(fmaxf(cy + 0.5f * bh, 0.f), Hf);

    bool valid = (x2 - x1 + 1.f >= 16.f) && (y2 - y1 + 1.f >= 16.f);

    float mx = fmaxf(s0, s1);
    float e0 = expf(s0 - mx), e1 = expf(s1 - mx);
    float fg = e1 / (e0 + e1);
    float score = valid ? fg : __int_as_float(0xff800000);  // -inf

    float* bp = &g_boxes[((size_t)b * NA + i) * 4];
    bp[0] = x1; bp[1] = y1; bp[2] = x2; bp[3] = y2;

    unsigned u = __float_as_uint(score);
    unsigned key = (u & 0x80000000u) ? ~u : (u | 0x80000000u);
    g_keys[(size_t)b * NA + i] = key;
    g_vals[(size_t)b * NA + i] = i;
}

// ---------------- gather top-3000 ----------------
__global__ void gather_kernel() {
    int t = blockIdx.x * blockDim.x + threadIdx.x;
    if (t >= NBATCH * NPRE) return;
    int b = t / NPRE, r = t % NPRE;
    unsigned key = g_keysOut[(size_t)b * NA + r];
    int i = g_valsOut[(size_t)b * NA + r];
    float4 box = reinterpret_cast<const float4*>(g_boxes)[(size_t)b * NA + i];
    reinterpret_cast<float4*>(g_top)[(size_t)b * NPRE + r] = box;
    g_topValid[(size_t)b * NPRE + r] = (key != 0x007FFFFFu) ? 1 : 0;  // key(-inf)=0x007FFFFF
}

// ---------------- IoU bitmask matrix ----------------
__global__ void __launch_bounds__(128) nms_mask_kernel() {
    __shared__ float4 sb[NPRE];
    int b = blockIdx.y;
    for (int t = threadIdx.x; t < NPRE; t += 128)
        sb[t] = reinterpret_cast<const float4*>(g_top)[(size_t)b * NPRE + t];
    __syncthreads();
    int i = blockIdx.x * 128 + threadIdx.x;
    if (i >= NPRE) return;
    float4 bi = sb[i];
    float ai = (bi.z - bi.x) * (bi.w - bi.y);
    unsigned* rowp = &g_nmsMask[((size_t)b * NPRE + i) * NWORDS];
    int jw0 = i >> 5;
    for (int jw = 0; jw < NWORDS; jw++) {
        unsigned bits = 0;
        if (jw >= jw0) {
            int jbase = jw * 32;
#pragma unroll 4
            for (int k = 0; k < 32; k++) {
                int j = jbase + k;
                if (j > i && j < NPRE) {
                    float4 bj = sb[j];
                    float iw = fmaxf(fminf(bi.z, bj.z) - fmaxf(bi.x, bj.x), 0.f);
                    float ih = fmaxf(fminf(bi.w, bj.w) - fmaxf(bi.y, bj.y), 0.f);
                    float inter = iw * ih;
                    float aj = (bj.z - bj.x) * (bj.w - bj.y);
                    float iou = inter / (ai + aj - inter + 1e-9f);
                    if (iou > 0.7f) bits |= 1u << k;
                }
            }
        }
        rowp[jw] = bits;
    }
}

// ---------------- serial greedy scan + emit rois ----------------
__global__ void __launch_bounds__(32) nms_scan_kernel(float* out) {
    __shared__ unsigned sup[96];
    __shared__ unsigned vbits[96];
    int b = blockIdx.x;
    int lane = threadIdx.x;

    for (int t = lane; t < NPOST * 4; t += 32)
        out[(size_t)OFF_ROIS + (size_t)b * NPOST * 4 + t] = 0.f;

#pragma unroll
    for (int q = 0; q < 3; q++) {
        int w = lane + 32 * q;
        sup[w] = 0;
        unsigned v = 0;
        if (w < NWORDS) {
            for (int k = 0; k < 32; k++) {
                int j = w * 32 + k;
                if (j < NPRE && g_topValid[(size_t)b * NPRE + j]) v |= 1u << k;
            }
        }
        vbits[w] = v;
    }
    __syncwarp();

    const unsigned* maskBase = &g_nmsMask[(size_t)b * NPRE * NWORDS];
    unsigned pre[4][3];
#pragma unroll
    for (int d = 0; d < 4; d++)
#pragma unroll
        for (int q = 0; q < 3; q++) {
            int w = lane + 32 * q;
            pre[d][q] = (w < NWORDS) ? maskBase[(size_t)d * NWORDS + w] : 0u;
        }
    __syncwarp();

    int cnt = 0;
    for (int i = 0; i < NPRE; i++) {
        int slot = i & 3;
        unsigned keep = 0;
        if (lane == 0) {
            unsigned sbit = (sup[i >> 5] >> (i & 31)) & 1u;
            unsigned vbit = (vbits[i >> 5] >> (i & 31)) & 1u;
            keep = vbit & (~sbit) & 1u;
        }
        keep = __shfl_sync(0xffffffffu, keep, 0);
        if (keep) {
#pragma unroll
            for (int q = 0; q < 3; q++) {
                int w = lane + 32 * q;
                if (w < NWORDS) sup[w] |= pre[slot][q];
            }
            if (lane < 4)
                out[(size_t)OFF_ROIS + ((size_t)b * NPOST + cnt) * 4 + lane] =
                    g_top[((size_t)b * NPRE + i) * 4 + lane];
            cnt++;
            if (cnt == NPOST) break;
        }
        int ip = i + 4;
#pragma unroll
        for (int q = 0; q < 3; q++) {
            int w = lane + 32 * q;
            pre[slot][q] = (ip < NPRE && w < NWORDS) ? maskBase[(size_t)ip * NWORDS + w] : 0u;
        }
        __syncwarp();
    }
}

// ---------------- roi indices ----------------
__global__ void ridx_kernel(float* out) {
    int t = blockIdx.x * blockDim.x + threadIdx.x;
    if (t < NBATCH * NPOST) out[(size_t)OFF_RIDX + t] = (float)(t / NPOST);
}

// ---------------- launch ----------------
extern "C" void kernel_launch(void* const* d_in, const int* in_sizes, int n_in,
                              void* d_out, int out_size) {
    const float* x = (const float*)d_in[0];
    const float* conv1_w = (const float*)d_in[1];
    const float* conv1_b = (const float*)d_in[2];
    const float* loc_w = (const float*)d_in[3];
    const float* loc_b = (const float*)d_in[4];
    const float* score_w = (const float*)d_in[5];
    const float* score_b = (const float*)d_in[6];
    const int* img_h = (const int*)d_in[7];
    const int* img_w = (const int*)d_in[8];
    float* out = (float*)d_out;

    wtrans_kernel<<<(512 * 9 * 512 + 255) / 256, 256>>>(conv1_w);
    hwtrans_kernel<<<(512 * 54 + 255) / 256, 256>>>(loc_w, score_w);

    cudaFuncSetAttribute(conv3x3_v2, cudaFuncAttributeMaxDynamicSharedMemorySize,
                         CONV_SMEM);
    conv3x3_v2<<<dim3(40, 2, NBATCH), 256, CONV_SMEM>>>(x, conv1_b);

    heads_kernel<<<625, 256>>>(loc_b, score_b, out);

    decode_kernel<<<(NBATCH * NA + 255) / 256, 256>>>(out, img_h, img_w);

    void *pKeys, *pKeysOut, *pVals, *pValsOut, *pSeg, *pTemp;
    cudaGetSymbolAddress(&pKeys, g_keys);
    cudaGetSymbolAddress(&pKeysOut, g_keysOut);
    cudaGetSymbolAddress(&pVals, g_vals);
    cudaGetSymbolAddress(&pValsOut, g_valsOut);
    cudaGetSymbolAddress(&pSeg, g_segOff);
    cudaGetSymbolAddress(&pTemp, g_cubTemp);

    size_t temp_bytes = 0;
    cub::DeviceSegmentedRadixSort::SortPairsDescending(
        nullptr, temp_bytes, (const unsigned*)pKeys, (unsigned*)pKeysOut,
        (const int*)pVals, (int*)pValsOut, NBATCH * NA, NBATCH,
        (const int*)pSeg, ((const int*)pSeg) + 1, 0, 32, (cudaStream_t)0);
    if (temp_bytes <= (size_t)(16 << 20)) {
        cub::DeviceSegmentedRadixSort::SortPairsDescending(
            pTemp, temp_bytes, (const unsigned*)pKeys, (unsigned*)pKeysOut,
            (const int*)pVals, (int*)pValsOut, NBATCH * NA, NBATCH,
            (const int*)pSeg, ((const int*)pSeg) + 1, 0, 32, (cudaStream_t)0);
    }

    gather_kernel<<<(NBATCH * NPRE + 255) / 256, 256>>>();
    nms_mask_kernel<<<dim3((NPRE + 127) / 128, NBATCH), 128>>>();
    nms_scan_kernel<<<NBATCH, 32>>>(out);
    ridx_kernel<<<(NBATCH * NPOST + 255) / 256, 256>>>(out);
}

// round 4
// speedup vs baseline: 1.0828x; 1.0320x over previous
#include <cuda_runtime.h>
#include <cub/cub.cuh>
#include <cstdint>
#include <math.h>

// ---------------- problem constants ----------------
#define NBATCH 4
#define FH 50
#define FW 50
#define CIN 512
#define COUT 512
#define NA 22500          // anchors per batch (50*50*9)
#define NPRE 3000
#define NPOST 300
#define NWORDS 94         // ceil(3000/32)

// output layout (flattened tuple, float32)
#define OFF_LOCS   0            // 4*22500*4 = 360000
#define OFF_SCORES 360000       // 4*22500*2 = 180000
#define OFF_ROIS   540000       // 4*300*4   = 4800
#define OFF_RIDX   544800       // 1200
#define OFF_ANCH   546000       // 22500*4   = 90000
// total 636000

// ---------------- device scratch ----------------
__device__ float g_feat[(size_t)NBATCH * 2500 * 512];   // NHWC feat
__device__ float g_wT[(size_t)512 * 9 * 512];            // [ci][tap][ko]
__device__ float g_hwT[(size_t)512 * 54];                // [k][c], c: 0..35 loc, 36..53 score
__device__ float g_boxes[(size_t)NBATCH * NA * 4];
__device__ unsigned long long g_keys64[(size_t)NBATCH * NA];
__device__ unsigned long long g_keysOut64[(size_t)NBATCH * NA];
__device__ int g_vals[(size_t)NBATCH * NA];
__device__ int g_valsOut[(size_t)NBATCH * NA];
__device__ float g_top[(size_t)NBATCH * NPRE * 4];
__device__ unsigned char g_topValid[(size_t)NBATCH * NPRE];
__device__ unsigned g_nmsMask[(size_t)NBATCH * NPRE * NWORDS];
__device__ unsigned char g_cubTemp[16 << 20];

// ---------------- weight transposes ----------------
__global__ void wtrans_kernel(const float* __restrict__ w) {
    int t = blockIdx.x * blockDim.x + threadIdx.x;
    if (t >= 512 * 9 * 512) return;
    int ko = t % 512;
    int tap = (t / 512) % 9;
    int ci = t / (512 * 9);
    g_wT[t] = w[((size_t)ko * 512 + ci) * 9 + tap];
}

__global__ void hwtrans_kernel(const float* __restrict__ loc_w,
                               const float* __restrict__ score_w) {
    int t = blockIdx.x * blockDim.x + threadIdx.x;
    if (t >= 512 * 54) return;
    int k = t / 54, c = t % 54;
    float v;
    if (c < 36) v = loc_w[(size_t)c * 512 + k];
    else        v = score_w[(size_t)(c - 36) * 512 + k];
    g_hwT[t] = v;
}

// ---------------- 3x3 conv + ReLU, register-tiled implicit GEMM v2 ----------
#define CONV_SIN  (8 * 5 * 52)      // 2080 floats
#define CONV_SW   (8 * 9 * 256)     // 18432 floats
#define CONV_SMEM ((CONV_SIN + CONV_SW) * 4)

__global__ void __launch_bounds__(256, 2) conv3x3_v2(const float* __restrict__ x,
                                                     const float* __restrict__ bias) {
    extern __shared__ float sm[];
    float* sIn = sm;                 // [ci][r][c] : ci*260 + r*52 + c
    float* sW = sm + CONV_SIN;       // [ci][tap][ko]: (ci*9+tap)*256 + ko

    int mt = blockIdx.x;             // 0..39
    int nt = blockIdx.y;             // 0..1
    int n = blockIdx.z;              // 0..3
    int s0 = mt * 64;
    int y0 = s0 / 50;
    int ko0 = nt * 256;
    int tid = threadIdx.x;
    int wid = tid >> 5, lane = tid & 31;
    int koL = lane * 8;

    int off[8], sglob[8];
#pragma unroll
    for (int j = 0; j < 8; j++) {
        int s = s0 + wid * 8 + j;
        int yy = s / 50, xx = s % 50;
        off[j] = (yy - y0 + 1) * 52 + xx + 1;
        sglob[j] = s;
    }

    float acc[8][8];
#pragma unroll
    for (int j = 0; j < 8; j++)
#pragma unroll
        for (int k = 0; k < 8; k++) acc[j][k] = 0.f;

    for (int c0 = 0; c0 < 512; c0 += 8) {
        __syncthreads();
        for (int t = tid; t < CONV_SIN; t += 256) {
            int ci = t / 260;
            int rem = t % 260;
            int r = rem / 52;
            int cc = rem % 52;
            int gy = y0 - 1 + r;
            int gx = cc - 1;
            float v = 0.f;
            if (gy >= 0 && gy < FH && gx >= 0 && gx < FW)
                v = x[(((size_t)n * 512 + c0 + ci) * FH + gy) * FW + gx];
            sIn[t] = v;
        }
        for (int t = tid; t < CONV_SW; t += 256) {
            int ko = t & 255;
            int rest = t >> 8;
            int tap = rest % 9;
            int ci = rest / 9;
            sW[t] = g_wT[((size_t)(c0 + ci) * 9 + tap) * 512 + ko0 + ko];
        }
        __syncthreads();

#pragma unroll 1
        for (int ci = 0; ci < 8; ci++) {
            const float* sIci = &sIn[ci * 260];
            const float* sWci = &sW[ci * 9 * 256 + koL];
#pragma unroll
            for (int dy = 0; dy < 3; dy++) {
#pragma unroll
                for (int dx = 0; dx < 3; dx++) {
                    int tap = dy * 3 + dx;
                    float4 w0 = *reinterpret_cast<const float4*>(&sWci[tap * 256]);
                    float4 w1 = *reinterpret_cast<const float4*>(&sWci[tap * 256 + 4]);
                    int d = (dy - 1) * 52 + (dx - 1);
                    float a[8];
#pragma unroll
                    for (int j = 0; j < 8; j++) a[j] = sIci[off[j] + d];
#pragma unroll
                    for (int j = 0; j < 8; j++) {
                        acc[j][0] += a[j] * w0.x;
                        acc[j][1] += a[j] * w0.y;
                        acc[j][2] += a[j] * w0.z;
                        acc[j][3] += a[j] * w0.w;
                        acc[j][4] += a[j] * w1.x;
                        acc[j][5] += a[j] * w1.y;
                        acc[j][6] += a[j] * w1.z;
                        acc[j][7] += a[j] * w1.w;
                    }
                }
            }
        }
    }

    float4 b0 = *reinterpret_cast<const float4*>(&bias[ko0 + koL]);
    float4 b1 = *reinterpret_cast<const float4*>(&bias[ko0 + koL + 4]);
#pragma unroll
    for (int j = 0; j < 8; j++) {
        if (sglob[j] < 2500) {
            float4 v0, v1;
            v0.x = fmaxf(acc[j][0] + b0.x, 0.f);
            v0.y = fmaxf(acc[j][1] + b0.y, 0.f);
            v0.z = fmaxf(acc[j][2] + b0.z, 0.f);
            v0.w = fmaxf(acc[j][3] + b0.w, 0.f);
            v1.x = fmaxf(acc[j][4] + b1.x, 0.f);
            v1.y = fmaxf(acc[j][5] + b1.y, 0.f);
            v1.z = fmaxf(acc[j][6] + b1.z, 0.f);
            v1.w = fmaxf(acc[j][7] + b1.w, 0.f);
            float* op = &g_feat[((size_t)n * 2500 + sglob[j]) * 512 + ko0 + koL];
            *reinterpret_cast<float4*>(op) = v0;
            *reinterpret_cast<float4*>(op + 4) = v1;
        }
    }
}

// ---------------- 1x1 heads (loc 36 + score 18) ----------------
__device__ __forceinline__ void write_head(float* out, int m, int c, float acc,
                                           const float* __restrict__ loc_b,
                                           const float* __restrict__ score_b) {
    int n = m / 2500, pos = m % 2500;
    if (c < 36) {
        int a = c >> 2, j = c & 3;
        out[(size_t)OFF_LOCS + ((size_t)n * NA + (size_t)pos * 9 + a) * 4 + j] = acc + loc_b[c];
    } else {
        int cc = c - 36;
        int a = cc >> 1, j = cc & 1;
        out[(size_t)OFF_SCORES + ((size_t)n * NA + (size_t)pos * 9 + a) * 2 + j] = acc + score_b[cc];
    }
}

__global__ void __launch_bounds__(256) heads_kernel(const float* __restrict__ loc_b,
                                                    const float* __restrict__ score_b,
                                                    float* out) {
    __shared__ float sf[16][512];
    int m0 = blockIdx.x * 16;
    int tid = threadIdx.x;
    for (int t = tid; t < 16 * 512; t += 256)
        sf[t >> 9][t & 511] = g_feat[((size_t)m0 << 9) + t];
    __syncthreads();
    int c = tid & 63;
    int mi = tid >> 6;  // 0..3
    if (c < 54) {
        float a0 = 0.f, a1 = 0.f, a2 = 0.f, a3 = 0.f;
#pragma unroll 4
        for (int k = 0; k < 512; k++) {
            float w = g_hwT[(size_t)k * 54 + c];
            a0 += sf[mi + 0][k] * w;
            a1 += sf[mi + 4][k] * w;
            a2 += sf[mi + 8][k] * w;
            a3 += sf[mi + 12][k] * w;
        }
        write_head(out, m0 + mi + 0, c, a0, loc_b, score_b);
        write_head(out, m0 + mi + 4, c, a1, loc_b, score_b);
        write_head(out, m0 + mi + 8, c, a2, loc_b, score_b);
        write_head(out, m0 + mi + 12, c, a3, loc_b, score_b);
    }
}

// ---------------- decode: anchors, loc2bbox, clip, valid, fg score ----------------
__global__ void decode_kernel(float* out, const int* __restrict__ imh,
                              const int* __restrict__ imw) {
    int t = blockIdx.x * blockDim.x + threadIdx.x;
    if (t >= NBATCH * NA) return;
    int b = t / NA, i = t % NA;
    int pos = i / 9, a = i % 9;
    int y = pos / 50, x = pos % 50;

    int ri = a / 3, si = a % 3;
    double rr = (ri == 0) ? 0.5 : ((ri == 1) ? 1.0 : 2.0);
    double ss = (si == 0) ? 8.0 : ((si == 1) ? 16.0 : 32.0);
    double hh = 16.0 * ss * sqrt(rr);
    double wwd = 16.0 * ss * sqrt(1.0 / rr);
    float b0 = (float)(8.0 - wwd * 0.5);
    float b1 = (float)(8.0 - hh * 0.5);
    float b2 = (float)(8.0 + wwd * 0.5);
    float b3 = (float)(8.0 + hh * 0.5);
    float sx = (float)(x * 16), sy = (float)(y * 16);
    float ax1 = sx + b0, ay1 = sy + b1, ax2 = sx + b2, ay2 = sy + b3;

    if (b == 0) {
        float* ap = &out[(size_t)OFF_ANCH + (size_t)i * 4];
        ap[0] = ax1; ap[1] = ay1; ap[2] = ax2; ap[3] = ay2;
    }

    const float* lp = &out[(size_t)OFF_LOCS + ((size_t)b * NA + i) * 4];
    float l0 = lp[0], l1 = lp[1], l2 = lp[2], l3 = lp[3];
    const float* spt = &out[(size_t)OFF_SCORES + ((size_t)b * NA + i) * 2];
    float s0 = spt[0], s1 = spt[1];

    float aw = ax2 - ax1, ah = ay2 - ay1;
    float acx = ax1 + 0.5f * aw, acy = ay1 + 0.5f * ah;
    float cx = l0 * aw + acx, cy = l1 * ah + acy;
    float bw = expf(l2) * aw, bh = expf(l3) * ah;

    float Wf = (float)imw[0], Hf = (float)imh[0];
    float x1 = fminf(fmaxf(cx - 0.5f * bw, 0.f), Wf);
    float y1 = fminf(fmaxf(cy - 0.5f * bh, 0.f), Hf);
    float x2 = fminf(fmaxf(cx + 0.5f * bw, 0.f), Wf);
    float y2 = fminf(fmaxf(cy + 0.5f * bh, 0.f), Hf);

    bool valid = (x2 - x1 + 1.f >= 16.f) && (y2 - y1 + 1.f >= 16.f);

    float mx = fmaxf(s0, s1);
    float e0 = expf(s0 - mx), e1 = expf(s1 - mx);
    float fg = e1 / (e0 + e1);
    float score = valid ? fg : __int_as_float(0xff800000);  // -inf

    float* bp = &g_boxes[((size_t)b * NA + i) * 4];
    bp[0] = x1; bp[1] = y1; bp[2] = x2; bp[3] = y2;

    // ascending-stable 64-bit key: [2b batch][32b ~flip(score)]
    // ascending key order == within batch: descending score, ties by index.
    unsigned u = __float_as_uint(score);
    unsigned flip = (u & 0x80000000u) ? ~u : (u | 0x80000000u);
    unsigned long long key = ((unsigned long long)b << 32) | (unsigned)(~flip);
    g_keys64[(size_t)b * NA + i] = key;
    g_vals[(size_t)b * NA + i] = i;
}

// ---------------- gather top-3000 ----------------
__global__ void gather_kernel() {
    int t = blockIdx.x * blockDim.x + threadIdx.x;
    if (t >= NBATCH * NPRE) return;
    int b = t / NPRE, r = t % NPRE;
    unsigned long long key = g_keysOut64[(size_t)b * NA + r];
    int i = g_valsOut[(size_t)b * NA + r];
    float4 box = reinterpret_cast<const float4*>(g_boxes)[(size_t)b * NA + i];
    reinterpret_cast<float4*>(g_top)[(size_t)b * NPRE + r] = box;
    // ~flip(-inf) = 0xff800000
    g_topValid[(size_t)b * NPRE + r] = ((unsigned)key != 0xff800000u) ? 1 : 0;
}

// ---------------- IoU bitmask matrix ----------------
__global__ void __launch_bounds__(128) nms_mask_kernel() {
    __shared__ float4 sb[NPRE];
    int b = blockIdx.y;
    for (int t = threadIdx.x; t < NPRE; t += 128)
        sb[t] = reinterpret_cast<const float4*>(g_top)[(size_t)b * NPRE + t];
    __syncthreads();
    int i = blockIdx.x * 128 + threadIdx.x;
    if (i >= NPRE) return;
    float4 bi = sb[i];
    float ai = (bi.z - bi.x) * (bi.w - bi.y);
    unsigned* rowp = &g_nmsMask[((size_t)b * NPRE + i) * NWORDS];
    int jw0 = i >> 5;
    for (int jw = 0; jw < NWORDS; jw++) {
        unsigned bits = 0;
        if (jw >= jw0) {
            int jbase = jw * 32;
#pragma unroll 4
            for (int k = 0; k < 32; k++) {
                int j = jbase + k;
                if (j > i && j < NPRE) {
                    float4 bj = sb[j];
                    float iw = fmaxf(fminf(bi.z, bj.z) - fmaxf(bi.x, bj.x), 0.f);
                    float ih = fmaxf(fminf(bi.w, bj.w) - fmaxf(bi.y, bj.y), 0.f);
                    float inter = iw * ih;
                    float aj = (bj.z - bj.x) * (bj.w - bj.y);
                    float iou = inter / (ai + aj - inter + 1e-9f);
                    if (iou > 0.7f) bits |= 1u << k;
                }
            }
        }
        rowp[jw] = bits;
    }
}

// ---------------- serial greedy scan + emit rois ----------------
__global__ void __launch_bounds__(32) nms_scan_kernel(float* out) {
    __shared__ unsigned sup[96];
    __shared__ unsigned vbits[96];
    int b = blockIdx.x;
    int lane = threadIdx.x;

    for (int t = lane; t < NPOST * 4; t += 32)
        out[(size_t)OFF_ROIS + (size_t)b * NPOST * 4 + t] = 0.f;

#pragma unroll
    for (int q = 0; q < 3; q++) {
        int w = lane + 32 * q;
        sup[w] = 0;
        unsigned v = 0;
        if (w < NWORDS) {
            for (int k = 0; k < 32; k++) {
                int j = w * 32 + k;
                if (j < NPRE && g_topValid[(size_t)b * NPRE + j]) v |= 1u << k;
            }
        }
        vbits[w] = v;
    }
    __syncwarp();

    const unsigned* maskBase = &g_nmsMask[(size_t)b * NPRE * NWORDS];
    unsigned pre[4][3];
#pragma unroll
    for (int d = 0; d < 4; d++)
#pragma unroll
        for (int q = 0; q < 3; q++) {
            int w = lane + 32 * q;
            pre[d][q] = (w < NWORDS) ? maskBase[(size_t)d * NWORDS + w] : 0u;
        }
    __syncwarp();

    int cnt = 0;
    for (int i = 0; i < NPRE; i++) {
        int slot = i & 3;
        unsigned keep = 0;
        if (lane == 0) {
            unsigned sbit = (sup[i >> 5] >> (i & 31)) & 1u;
            unsigned vbit = (vbits[i >> 5] >> (i & 31)) & 1u;
            keep = vbit & (~sbit) & 1u;
        }
        keep = __shfl_sync(0xffffffffu, keep, 0);
        if (keep) {
#pragma unroll
            for (int q = 0; q < 3; q++) {
                int w = lane + 32 * q;
                if (w < NWORDS) sup[w] |= pre[slot][q];
            }
            if (lane < 4)
                out[(size_t)OFF_ROIS + ((size_t)b * NPOST + cnt) * 4 + lane] =
                    g_top[((size_t)b * NPRE + i) * 4 + lane];
            cnt++;
            if (cnt == NPOST) break;
        }
        int ip = i + 4;
#pragma unroll
        for (int q = 0; q < 3; q++) {
            int w = lane + 32 * q;
            pre[slot][q] = (ip < NPRE && w < NWORDS) ? maskBase[(size_t)ip * NWORDS + w] : 0u;
        }
        __syncwarp();
    }
}

// ---------------- roi indices ----------------
__global__ void ridx_kernel(float* out) {
    int t = blockIdx.x * blockDim.x + threadIdx.x;
    if (t < NBATCH * NPOST) out[(size_t)OFF_RIDX + t] = (float)(t / NPOST);
}

// ---------------- launch ----------------
extern "C" void kernel_launch(void* const* d_in, const int* in_sizes, int n_in,
                              void* d_out, int out_size) {
    const float* x = (const float*)d_in[0];
    const float* conv1_w = (const float*)d_in[1];
    const float* conv1_b = (const float*)d_in[2];
    const float* loc_w = (const float*)d_in[3];
    const float* loc_b = (const float*)d_in[4];
    const float* score_w = (const float*)d_in[5];
    const float* score_b = (const float*)d_in[6];
    const int* img_h = (const int*)d_in[7];
    const int* img_w = (const int*)d_in[8];
    float* out = (float*)d_out;

    wtrans_kernel<<<(512 * 9 * 512 + 255) / 256, 256>>>(conv1_w);
    hwtrans_kernel<<<(512 * 54 + 255) / 256, 256>>>(loc_w, score_w);

    cudaFuncSetAttribute(conv3x3_v2, cudaFuncAttributeMaxDynamicSharedMemorySize,
                         CONV_SMEM);
    conv3x3_v2<<<dim3(40, 2, NBATCH), 256, CONV_SMEM>>>(x, conv1_b);

    heads_kernel<<<625, 256>>>(loc_b, score_b, out);

    decode_kernel<<<(NBATCH * NA + 255) / 256, 256>>>(out, img_h, img_w);

    // single full-device stable radix sort: key [2b batch | 32b ~flip(score)],
    // ascending over bits [0,34). Within each batch: descending score,
    // stable (index-ascending ties) — exactly lax.top_k semantics.
    void *pKeys, *pKeysOut, *pVals, *pValsOut, *pTemp;
    cudaGetSymbolAddress(&pKeys, g_keys64);
    cudaGetSymbolAddress(&pKeysOut, g_keysOut64);
    cudaGetSymbolAddress(&pVals, g_vals);
    cudaGetSymbolAddress(&pValsOut, g_valsOut);
    cudaGetSymbolAddress(&pTemp, g_cubTemp);

    size_t temp_bytes = 0;
    cub::DeviceRadixSort::SortPairs(
        nullptr, temp_bytes,
        (const unsigned long long*)pKeys, (unsigned long long*)pKeysOut,
        (const int*)pVals, (int*)pValsOut, NBATCH * NA, 0, 34, (cudaStream_t)0);
    if (temp_bytes <= (size_t)(16 << 20)) {
        cub::DeviceRadixSort::SortPairs(
            pTemp, temp_bytes,
            (const unsigned long long*)pKeys, (unsigned long long*)pKeysOut,
            (const int*)pVals, (int*)pValsOut, NBATCH * NA, 0, 34, (cudaStream_t)0);
    }

    gather_kernel<<<(NBATCH * NPRE + 255) / 256, 256>>>();
    nms_mask_kernel<<<dim3((NPRE + 127) / 128, NBATCH), 128>>>();
    nms_scan_kernel<<<NBATCH, 32>>>(out);
    ridx_kernel<<<(NBATCH * NPOST + 255) / 256, 256>>>(out);
}

// round 5
// speedup vs baseline: 1.4299x; 1.3206x over previous
#include <cuda_runtime.h>
#include <cub/cub.cuh>
#include <cstdint>
#include <math.h>

// ---------------- problem constants ----------------
#define NBATCH 4
#define FH 50
#define FW 50
#define NA 22500          // anchors per batch (50*50*9)
#define NPRE 3000
#define NPOST 300
#define NWORDS 94         // ceil(3000/32)

// output layout (flattened tuple, float32)
#define OFF_LOCS   0            // 4*22500*4 = 360000
#define OFF_SCORES 360000       // 4*22500*2 = 180000
#define OFF_ROIS   540000       // 4*300*4   = 4800
#define OFF_RIDX   544800       // 1200
#define OFF_ANCH   546000       // 22500*4   = 90000

// ---------------- device scratch ----------------
__device__ float g_feat[(size_t)NBATCH * 2500 * 512];   // NHWC feat
__device__ float g_wT[(size_t)512 * 9 * 512];            // [ci][tap][ko]
__device__ float g_hwT[(size_t)512 * 54];                // [k][c]
__device__ float g_boxes[(size_t)NBATCH * NA * 4];
__device__ unsigned long long g_keys64[(size_t)NBATCH * NA];
__device__ unsigned long long g_keysOut64[(size_t)NBATCH * NA];
__device__ int g_vals[(size_t)NBATCH * NA];
__device__ int g_valsOut[(size_t)NBATCH * NA];
__device__ float g_top[(size_t)NBATCH * NPRE * 4];
__device__ unsigned char g_topValid[(size_t)NBATCH * NPRE];
__device__ unsigned g_nmsMask[(size_t)NBATCH * NPRE * NWORDS];
__device__ unsigned char g_cubTemp[16 << 20];

// packed fp32x2 FMA: d.lo = a.lo*b.lo+d.lo ; d.hi = a.hi*b.hi+d.hi (exact fp32)
#define FMA2(d, a, w) \
    asm("fma.rn.f32x2 %0, %1, %2, %3;" : "=l"(d) : "l"(a), "l"(w), "l"(d))

// ---------------- weight transposes ----------------
__global__ void wtrans_kernel(const float* __restrict__ w) {
    int t = blockIdx.x * blockDim.x + threadIdx.x;
    if (t >= 512 * 9 * 512) return;
    int ko = t % 512;
    int tap = (t / 512) % 9;
    int ci = t / (512 * 9);
    g_wT[t] = w[((size_t)ko * 512 + ci) * 9 + tap];
}

__global__ void hwtrans_kernel(const float* __restrict__ loc_w,
                               const float* __restrict__ score_w) {
    int t = blockIdx.x * blockDim.x + threadIdx.x;
    if (t >= 512 * 54) return;
    int k = t / 54, c = t % 54;
    float v;
    if (c < 36) v = loc_w[(size_t)c * 512 + k];
    else        v = score_w[(size_t)(c - 36) * 512 + k];
    g_hwT[t] = v;
}

// ---------------- 3x3 conv + ReLU, packed f32x2 implicit GEMM v3 ----------
// Block: 64 spatial x 256 ko, 256 threads.
// warp w -> 8 spatial positions; lane l -> ko {4l..4l+3} U {128+4l..128+4l+3}.
// Thread: 8 sp x 8 ko = 64 fp32 accs held as 32 packed u64.
// smem: input tile DUPLICATED as (v,v) float2 (a-operand = one LDS.64),
//       weights [8ci][9tap][256ko] (lane loads = conflict-free ld.v2.u64).
#define CONV_SIN   (8 * 5 * 52)                      // logical floats: 2080
#define CONV_SW    (8 * 9 * 256)                     // 18432 floats
#define CONV_SMEM  (CONV_SIN * 8 + CONV_SW * 4)      // 16640 + 73728 = 90368 B

__global__ void __launch_bounds__(256, 2) conv3x3_v3(const float* __restrict__ x,
                                                     const float* __restrict__ bias) {
    extern __shared__ unsigned char smraw[];
    float2* sIn2 = reinterpret_cast<float2*>(smraw);            // [2080] dup pairs
    float* sW = reinterpret_cast<float*>(smraw + CONV_SIN * 8); // [18432]

    int mt = blockIdx.x;             // 0..39
    int nt = blockIdx.y;             // 0..1
    int n = blockIdx.z;              // 0..3
    int s0 = mt * 64;
    int y0 = s0 / 50;
    int ko0 = nt * 256;
    int tid = threadIdx.x;
    int wid = tid >> 5, lane = tid & 31;

    int off[8], sglob[8];
#pragma unroll
    for (int j = 0; j < 8; j++) {
        int s = s0 + wid * 8 + j;
        int yy = s / 50, xx = s % 50;
        off[j] = (yy - y0 + 1) * 52 + xx + 1;
        sglob[j] = s;
    }

    unsigned long long acc[8][4];
#pragma unroll
    for (int j = 0; j < 8; j++)
#pragma unroll
        for (int k = 0; k < 4; k++) acc[j][k] = 0ull;

    const unsigned long long* aBase =
        reinterpret_cast<const unsigned long long*>(sIn2);

    for (int c0 = 0; c0 < 512; c0 += 8) {
        __syncthreads();
        // input tile (duplicated pairs): rows y0-1..y0+3, cols -1..50
        for (int t = tid; t < CONV_SIN; t += 256) {
            int ci = t / 260;
            int rem = t % 260;
            int r = rem / 52;
            int cc = rem % 52;
            int gy = y0 - 1 + r;
            int gx = cc - 1;
            float v = 0.f;
            if (gy >= 0 && gy < FH && gx >= 0 && gx < FW)
                v = x[(((size_t)n * 512 + c0 + ci) * FH + gy) * FW + gx];
            sIn2[t] = make_float2(v, v);
        }
        // weights for this ci-chunk, all 9 taps
        for (int t = tid; t < CONV_SW; t += 256) {
            int ko = t & 255;
            int rest = t >> 8;
            int tap = rest % 9;
            int ci = rest / 9;
            sW[t] = g_wT[((size_t)(c0 + ci) * 9 + tap) * 512 + ko0 + ko];
        }
        __syncthreads();

#pragma unroll 1
        for (int ci = 0; ci < 8; ci++) {
            const unsigned long long* aci = aBase + ci * 260;
            const float* wci = sW + ci * 9 * 256 + 4 * lane;
#pragma unroll
            for (int dy = 0; dy < 3; dy++) {
#pragma unroll
                for (int dx = 0; dx < 3; dx++) {
                    int tap = dy * 3 + dx;
                    ulonglong2 wA = *reinterpret_cast<const ulonglong2*>(wci + tap * 256);
                    ulonglong2 wB = *reinterpret_cast<const ulonglong2*>(wci + tap * 256 + 128);
                    int d = (dy - 1) * 52 + (dx - 1);
#pragma unroll
                    for (int j = 0; j < 8; j++) {
                        unsigned long long av = aci[off[j] + d];
                        FMA2(acc[j][0], av, wA.x);
                        FMA2(acc[j][1], av, wA.y);
                        FMA2(acc[j][2], av, wB.x);
                        FMA2(acc[j][3], av, wB.y);
                    }
                }
            }
        }
    }

    // epilogue: + bias, ReLU, store NHWC
    float4 b0 = *reinterpret_cast<const float4*>(&bias[ko0 + 4 * lane]);
    float4 b1 = *reinterpret_cast<const float4*>(&bias[ko0 + 128 + 4 * lane]);
#pragma unroll
    for (int j = 0; j < 8; j++) {
        if (sglob[j] < 2500) {
            float2 p0 = *reinterpret_cast<float2*>(&acc[j][0]);
            float2 p1 = *reinterpret_cast<float2*>(&acc[j][1]);
            float2 p2 = *reinterpret_cast<float2*>(&acc[j][2]);
            float2 p3 = *reinterpret_cast<float2*>(&acc[j][3]);
            float4 v0, v1;
            v0.x = fmaxf(p0.x + b0.x, 0.f);
            v0.y = fmaxf(p0.y + b0.y, 0.f);
            v0.z = fmaxf(p1.x + b0.z, 0.f);
            v0.w = fmaxf(p1.y + b0.w, 0.f);
            v1.x = fmaxf(p2.x + b1.x, 0.f);
            v1.y = fmaxf(p2.y + b1.y, 0.f);
            v1.z = fmaxf(p3.x + b1.z, 0.f);
            v1.w = fmaxf(p3.y + b1.w, 0.f);
            float* op = &g_feat[((size_t)n * 2500 + sglob[j]) * 512 + ko0];
            *reinterpret_cast<float4*>(op + 4 * lane) = v0;
            *reinterpret_cast<float4*>(op + 128 + 4 * lane) = v1;
        }
    }
}

// ---------------- 1x1 heads (loc 36 + score 18) ----------------
__device__ __forceinline__ void write_head(float* out, int m, int c, float acc,
                                           const float* __restrict__ loc_b,
                                           const float* __restrict__ score_b) {
    int n = m / 2500, pos = m % 2500;
    if (c < 36) {
        int a = c >> 2, j = c & 3;
        out[(size_t)OFF_LOCS + ((size_t)n * NA + (size_t)pos * 9 + a) * 4 + j] = acc + loc_b[c];
    } else {
        int cc = c - 36;
        int a = cc >> 1, j = cc & 1;
        out[(size_t)OFF_SCORES + ((size_t)n * NA + (size_t)pos * 9 + a) * 2 + j] = acc + score_b[cc];
    }
}

__global__ void __launch_bounds__(256) heads_kernel(const float* __restrict__ loc_b,
                                                    const float* __restrict__ score_b,
                                                    float* out) {
    __shared__ float sf[16][512];
    int m0 = blockIdx.x * 16;
    int tid = threadIdx.x;
    for (int t = tid; t < 16 * 512; t += 256)
        sf[t >> 9][t & 511] = g_feat[((size_t)m0 << 9) + t];
    __syncthreads();
    int c = tid & 63;
    int mi = tid >> 6;
    if (c < 54) {
        float a0 = 0.f, a1 = 0.f, a2 = 0.f, a3 = 0.f;
#pragma unroll 4
        for (int k = 0; k < 512; k++) {
            float w = g_hwT[(size_t)k * 54 + c];
            a0 += sf[mi + 0][k] * w;
            a1 += sf[mi + 4][k] * w;
            a2 += sf[mi + 8][k] * w;
            a3 += sf[mi + 12][k] * w;
        }
        write_head(out, m0 + mi + 0, c, a0, loc_b, score_b);
        write_head(out, m0 + mi + 4, c, a1, loc_b, score_b);
        write_head(out, m0 + mi + 8, c, a2, loc_b, score_b);
        write_head(out, m0 + mi + 12, c, a3, loc_b, score_b);
    }
}

// ---------------- decode ----------------
__global__ void decode_kernel(float* out, const int* __restrict__ imh,
                              const int* __restrict__ imw) {
    int t = blockIdx.x * blockDim.x + threadIdx.x;
    if (t >= NBATCH * NA) return;
    int b = t / NA, i = t % NA;
    int pos = i / 9, a = i % 9;
    int y = pos / 50, x = pos % 50;

    int ri = a / 3, si = a % 3;
    double rr = (ri == 0) ? 0.5 : ((ri == 1) ? 1.0 : 2.0);
    double ss = (si == 0) ? 8.0 : ((si == 1) ? 16.0 : 32.0);
    double hh = 16.0 * ss * sqrt(rr);
    double wwd = 16.0 * ss * sqrt(1.0 / rr);
    float b0 = (float)(8.0 - wwd * 0.5);
    float b1 = (float)(8.0 - hh * 0.5);
    float b2 = (float)(8.0 + wwd * 0.5);
    float b3 = (float)(8.0 + hh * 0.5);
    float sx = (float)(x * 16), sy = (float)(y * 16);
    float ax1 = sx + b0, ay1 = sy + b1, ax2 = sx + b2, ay2 = sy + b3;

    if (b == 0) {
        float* ap = &out[(size_t)OFF_ANCH + (size_t)i * 4];
        ap[0] = ax1; ap[1] = ay1; ap[2] = ax2; ap[3] = ay2;
    }

    const float* lp = &out[(size_t)OFF_LOCS + ((size_t)b * NA + i) * 4];
    float l0 = lp[0], l1 = lp[1], l2 = lp[2], l3 = lp[3];
    const float* spt = &out[(size_t)OFF_SCORES + ((size_t)b * NA + i) * 2];
    float s0 = spt[0], s1 = spt[1];

    float aw = ax2 - ax1, ah = ay2 - ay1;
    float acx = ax1 + 0.5f * aw, acy = ay1 + 0.5f * ah;
    float cx = l0 * aw + acx, cy = l1 * ah + acy;
    float bw = expf(l2) * aw, bh = expf(l3) * ah;

    float Wf = (float)imw[0], Hf = (float)imh[0];
    float x1 = fminf(fmaxf(cx - 0.5f * bw, 0.f), Wf);
    float y1 = fminf(fmaxf(cy - 0.5f * bh, 0.f), Hf);
    float x2 = fminf(fmaxf(cx + 0.5f * bw, 0.f), Wf);
    float y2 = fminf(fmaxf(cy + 0.5f * bh, 0.f), Hf);

    bool valid = (x2 - x1 + 1.f >= 16.f) && (y2 - y1 + 1.f >= 16.f);

    float mx = fmaxf(s0, s1);
    float e0 = expf(s0 - mx), e1 = expf(s1 - mx);
    float fg = e1 / (e0 + e1);
    float score = valid ? fg : __int_as_float(0xff800000);  // -inf

    float* bp = &g_boxes[((size_t)b * NA + i) * 4];
    bp[0] = x1; bp[1] = y1; bp[2] = x2; bp[3] = y2;

    // ascending-stable 64-bit key: [2b batch][32b ~flip(score)]
    unsigned u = __float_as_uint(score);
    unsigned flip = (u & 0x80000000u) ? ~u : (u | 0x80000000u);
    unsigned long long key = ((unsigned long long)b << 32) | (unsigned)(~flip);
    g_keys64[(size_t)b * NA + i] = key;
    g_vals[(size_t)b * NA + i] = i;
}

// ---------------- gather top-3000 ----------------
__global__ void gather_kernel() {
    int t = blockIdx.x * blockDim.x + threadIdx.x;
    if (t >= NBATCH * NPRE) return;
    int b = t / NPRE, r = t % NPRE;
    unsigned long long key = g_keysOut64[(size_t)b * NA + r];
    int i = g_valsOut[(size_t)b * NA + r];
    float4 box = reinterpret_cast<const float4*>(g_boxes)[(size_t)b * NA + i];
    reinterpret_cast<float4*>(g_top)[(size_t)b * NPRE + r] = box;
    g_topValid[(size_t)b * NPRE + r] = ((unsigned)key != 0xff800000u) ? 1 : 0;
}

// ---------------- IoU bitmask matrix (division-free) ----------------
__global__ void __launch_bounds__(128) nms_mask_kernel() {
    __shared__ float4 sb[NPRE];
    int b = blockIdx.y;
    for (int t = threadIdx.x; t < NPRE; t += 128)
        sb[t] = reinterpret_cast<const float4*>(g_top)[(size_t)b * NPRE + t];
    __syncthreads();
    int i = blockIdx.x * 128 + threadIdx.x;
    if (i >= NPRE) return;
    float4 bi = sb[i];
    float ai = (bi.z - bi.x) * (bi.w - bi.y);
    unsigned* rowp = &g_nmsMask[((size_t)b * NPRE + i) * NWORDS];
    int jw0 = i >> 5;
    for (int jw = 0; jw < NWORDS; jw++) {
        unsigned bits = 0;
        if (jw >= jw0) {
            int jbase = jw * 32;
#pragma unroll 4
            for (int k = 0; k < 32; k++) {
                int j = jbase + k;
                if (j > i && j < NPRE) {
                    float4 bj = sb[j];
                    float iw = fmaxf(fminf(bi.z, bj.z) - fmaxf(bi.x, bj.x), 0.f);
                    float ih = fmaxf(fminf(bi.w, bj.w) - fmaxf(bi.y, bj.y), 0.f);
                    float inter = iw * ih;
                    float aj = (bj.z - bj.x) * (bj.w - bj.y);
                    // iou > 0.7  <=>  inter > 0.7*(union + 1e-9)
                    if (inter > 0.7f * (ai + aj - inter + 1e-9f)) bits |= 1u << k;
                }
            }
        }
        rowp[jw] = bits;
    }
}

// ---------------- greedy scan v2: ffs skip over suppressed ----------------
__global__ void __launch_bounds__(32) nms_scan_kernel(float* out) {
    __shared__ unsigned sup[96];
    __shared__ unsigned vb[96];
    int b = blockIdx.x;
    int lane = threadIdx.x;

    for (int t = lane; t < NPOST * 4; t += 32)
        out[(size_t)OFF_ROIS + (size_t)b * NPOST * 4 + t] = 0.f;

#pragma unroll
    for (int q = 0; q < 3; q++) {
        int w = lane + 32 * q;
        sup[w] = 0;
        unsigned v = 0;
        if (w < NWORDS) {
            for (int k = 0; k < 32; k++) {
                int j = w * 32 + k;
                if (j < NPRE && g_topValid[(size_t)b * NPRE + j]) v |= 1u << k;
            }
        }
        vb[w] = v;
    }
    __syncwarp();

    const unsigned* maskBase = &g_nmsMask[(size_t)b * NPRE * NWORDS];
    int cnt = 0;
    int i = 0;
    while (cnt < NPOST) {
        int w = i >> 5;
        if (w >= NWORDS) break;
        unsigned live = (vb[w] & ~sup[w]) & (0xFFFFFFFFu << (i & 31));
        while (live == 0) {
            if (++w >= NWORDS) { w = -1; break; }
            live = vb[w] & ~sup[w];
        }
        if (w < 0) break;
        i = w * 32 + (__ffs(live) - 1);

        if (lane < 4)
            out[(size_t)OFF_ROIS + ((size_t)b * NPOST + cnt) * 4 + lane] =
                g_top[((size_t)b * NPRE + i) * 4 + lane];
        cnt++;

        const unsigned* row = maskBase + (size_t)i * NWORDS;
#pragma unroll
        for (int q = 0; q < 3; q++) {
            int ww = lane + 32 * q;
            if (ww < NWORDS) sup[ww] |= row[ww];
        }
        __syncwarp();
        i++;
    }
}

// ---------------- roi indices ----------------
__global__ void ridx_kernel(float* out) {
    int t = blockIdx.x * blockDim.x + threadIdx.x;
    if (t < NBATCH * NPOST) out[(size_t)OFF_RIDX + t] = (float)(t / NPOST);
}

// ---------------- launch ----------------
extern "C" void kernel_launch(void* const* d_in, const int* in_sizes, int n_in,
                              void* d_out, int out_size) {
    const float* x = (const float*)d_in[0];
    const float* conv1_w = (const float*)d_in[1];
    const float* conv1_b = (const float*)d_in[2];
    const float* loc_w = (const float*)d_in[3];
    const float* loc_b = (const float*)d_in[4];
    const float* score_w = (const float*)d_in[5];
    const float* score_b = (const float*)d_in[6];
    const int* img_h = (const int*)d_in[7];
    const int* img_w = (const int*)d_in[8];
    float* out = (float*)d_out;

    wtrans_kernel<<<(512 * 9 * 512 + 255) / 256, 256>>>(conv1_w);
    hwtrans_kernel<<<(512 * 54 + 255) / 256, 256>>>(loc_w, score_w);

    cudaFuncSetAttribute(conv3x3_v3, cudaFuncAttributeMaxDynamicSharedMemorySize,
                         CONV_SMEM);
    conv3x3_v3<<<dim3(40, 2, NBATCH), 256, CONV_SMEM>>>(x, conv1_b);

    heads_kernel<<<625, 256>>>(loc_b, score_b, out);

    decode_kernel<<<(NBATCH * NA + 255) / 256, 256>>>(out, img_h, img_w);

    // single full-device stable radix sort over [2b batch | 32b ~flip(score)]
    void *pKeys, *pKeysOut, *pVals, *pValsOut, *pTemp;
    cudaGetSymbolAddress(&pKeys, g_keys64);
    cudaGetSymbolAddress(&pKeysOut, g_keysOut64);
    cudaGetSymbolAddress(&pVals, g_vals);
    cudaGetSymbolAddress(&pValsOut, g_valsOut);
    cudaGetSymbolAddress(&pTemp, g_cubTemp);

    size_t temp_bytes = 0;
    cub::DeviceRadixSort::SortPairs(
        nullptr, temp_bytes,
        (const unsigned long long*)pKeys, (unsigned long long*)pKeysOut,
        (const int*)pVals, (int*)pValsOut, NBATCH * NA, 0, 34, (cudaStream_t)0);
    if (temp_bytes <= (size_t)(16 << 20)) {
        cub::DeviceRadixSort::SortPairs(
            pTemp, temp_bytes,
            (const unsigned long long*)pKeys, (unsigned long long*)pKeysOut,
            (const int*)pVals, (int*)pValsOut, NBATCH * NA, 0, 34, (cudaStream_t)0);
    }

    gather_kernel<<<(NBATCH * NPRE + 255) / 256, 256>>>();
    nms_mask_kernel<<<dim3((NPRE + 127) / 128, NBATCH), 128>>>();
    nms_scan_kernel<<<NBATCH, 32>>>(out);
    ridx_kernel<<<(NBATCH * NPOST + 255) / 256, 256>>>(out);
}

// round 6
// speedup vs baseline: 1.7864x; 1.2494x over previous
#include <cuda_runtime.h>
#include <cub/cub.cuh>
#include <cstdint>
#include <math.h>

// ---------------- problem constants ----------------
#define NBATCH 4
#define FH 50
#define FW 50
#define NA 22500          // anchors per batch (50*50*9)
#define NPRE 3000
#define NPOST 300
#define NWORDS 94         // ceil(3000/32)

// output layout (flattened tuple, float32)
#define OFF_LOCS   0            // 4*22500*4 = 360000
#define OFF_SCORES 360000       // 4*22500*2 = 180000
#define OFF_ROIS   540000       // 4*300*4   = 4800
#define OFF_RIDX   544800       // 1200
#define OFF_ANCH   546000       // 22500*4   = 90000

// ---------------- device scratch ----------------
__device__ float g_feat[(size_t)NBATCH * 2500 * 512];   // NHWC feat
__device__ float g_wT[(size_t)512 * 9 * 512];            // [ci][tap][ko]
__device__ float g_hwT[(size_t)512 * 54];                // [k][c]
__device__ float g_boxes[(size_t)NBATCH * NA * 4];
__device__ unsigned g_keys32[(size_t)NBATCH * NA];
__device__ unsigned g_keysOut32[(size_t)NBATCH * NA];
__device__ int g_vals[(size_t)NBATCH * NA];
__device__ int g_valsOut[(size_t)NBATCH * NA];
__device__ float g_top[(size_t)NBATCH * NPRE * 4];
__device__ unsigned char g_topValid[(size_t)NBATCH * NPRE];
__device__ unsigned g_nmsMask[(size_t)NBATCH * NPRE * NWORDS];
__device__ unsigned char g_cubTemp[16 << 20];

// packed fp32x2 FMA: d.lo = a.lo*b.lo+d.lo ; d.hi = a.hi*b.hi+d.hi (exact fp32)
#define FMA2(d, a, w) \
    asm("fma.rn.f32x2 %0, %1, %2, %3;" : "=l"(d) : "l"(a), "l"(w), "l"(d))

// ---------------- dummy (shifts ncu capture slot onto the conv) ----------
__global__ void dummy_k() {}

// ---------------- weight transposes ----------------
__global__ void wtrans_kernel(const float* __restrict__ w) {
    int t = blockIdx.x * blockDim.x + threadIdx.x;
    if (t >= 512 * 9 * 512) return;
    int ko = t % 512;
    int tap = (t / 512) % 9;
    int ci = t / (512 * 9);
    g_wT[t] = w[((size_t)ko * 512 + ci) * 9 + tap];
}

__global__ void hwtrans_kernel(const float* __restrict__ loc_w,
                               const float* __restrict__ score_w) {
    int t = blockIdx.x * blockDim.x + threadIdx.x;
    if (t >= 512 * 54) return;
    int k = t / 54, c = t % 54;
    float v;
    if (c < 36) v = loc_w[(size_t)c * 512 + k];
    else        v = score_w[(size_t)(c - 36) * 512 + k];
    g_hwT[t] = v;
}

// ---------------- 3x3 conv + ReLU, f32x2 implicit GEMM v4 ----------------
// Grid 35 x 2 x 4 = 280 blocks -> exactly one wave at 2 CTA/SM (296 slots).
// Block: 72 spatial x 256 ko, 256 threads. warp w -> 9 spatial positions,
// lane l -> ko {4l..4l+3} U {128+4l..128+4l+3}. Thread: 9sp x 8ko accs.
#define CONV_SIN   (8 * 5 * 52)                      // dup pairs: 2080
#define CONV_SW    (8 * 9 * 256)                     // 18432 floats
#define CONV_SMEM  (CONV_SIN * 8 + CONV_SW * 4)      // 90368 B

__global__ void __launch_bounds__(256, 2) conv3x3_v4(const float* __restrict__ x,
                                                     const float* __restrict__ bias) {
    extern __shared__ unsigned char smraw[];
    float2* sIn2 = reinterpret_cast<float2*>(smraw);            // dup pairs
    float* sW = reinterpret_cast<float*>(smraw + CONV_SIN * 8);

    int mt = blockIdx.x;             // 0..34
    int nt = blockIdx.y;             // 0..1
    int n = blockIdx.z;              // 0..3
    int s0 = mt * 72;
    int y0 = s0 / 50;
    int ko0 = nt * 256;
    int tid = threadIdx.x;
    int wid = tid >> 5, lane = tid & 31;

    int off[9];
#pragma unroll
    for (int j = 0; j < 9; j++) {
        int s = s0 + wid * 9 + j;
        int sc = s < 2499 ? s : 2499;   // clamp for addressing; store guarded
        int yy = sc / 50, xx = sc % 50;
        off[j] = (yy - y0 + 1) * 52 + xx + 1;
    }

    unsigned long long acc[9][4];
#pragma unroll
    for (int j = 0; j < 9; j++)
#pragma unroll
        for (int k = 0; k < 4; k++) acc[j][k] = 0ull;

    const unsigned long long* aBase =
        reinterpret_cast<const unsigned long long*>(sIn2);

    for (int c0 = 0; c0 < 512; c0 += 8) {
        __syncthreads();
        // input tile (duplicated pairs): rows y0-1..y0+3, cols -1..50
        for (int t = tid; t < CONV_SIN; t += 256) {
            int ci = t / 260;
            int rem = t % 260;
            int r = rem / 52;
            int cc = rem % 52;
            int gy = y0 - 1 + r;
            int gx = cc - 1;
            float v = 0.f;
            if (gy >= 0 && gy < FH && gx >= 0 && gx < FW)
                v = x[(((size_t)n * 512 + c0 + ci) * FH + gy) * FW + gx];
            sIn2[t] = make_float2(v, v);
        }
        // weights for this ci-chunk, all 9 taps
        for (int t = tid; t < CONV_SW; t += 256) {
            int ko = t & 255;
            int rest = t >> 8;
            int tap = rest % 9;
            int ci = rest / 9;
            sW[t] = g_wT[((size_t)(c0 + ci) * 9 + tap) * 512 + ko0 + ko];
        }
        __syncthreads();

#pragma unroll 1
        for (int ci = 0; ci < 8; ci++) {
            const unsigned long long* aci = aBase + ci * 260;
            const float* wci = sW + ci * 9 * 256 + 4 * lane;
#pragma unroll
            for (int dy = 0; dy < 3; dy++) {
#pragma unroll
                for (int dx = 0; dx < 3; dx++) {
                    int tap = dy * 3 + dx;
                    ulonglong2 wA = *reinterpret_cast<const ulonglong2*>(wci + tap * 256);
                    ulonglong2 wB = *reinterpret_cast<const ulonglong2*>(wci + tap * 256 + 128);
                    int d = (dy - 1) * 52 + (dx - 1);
#pragma unroll
                    for (int j = 0; j < 9; j++) {
                        unsigned long long av = aci[off[j] + d];
                        FMA2(acc[j][0], av, wA.x);
                        FMA2(acc[j][1], av, wA.y);
                        FMA2(acc[j][2], av, wB.x);
                        FMA2(acc[j][3], av, wB.y);
                    }
                }
            }
        }
    }

    // epilogue: + bias, ReLU, store NHWC
    float4 b0 = *reinterpret_cast<const float4*>(&bias[ko0 + 4 * lane]);
    float4 b1 = *reinterpret_cast<const float4*>(&bias[ko0 + 128 + 4 * lane]);
#pragma unroll
    for (int j = 0; j < 9; j++) {
        int s = s0 + wid * 9 + j;
        if (s < 2500) {
            float2 p0 = *reinterpret_cast<float2*>(&acc[j][0]);
            float2 p1 = *reinterpret_cast<float2*>(&acc[j][1]);
            float2 p2 = *reinterpret_cast<float2*>(&acc[j][2]);
            float2 p3 = *reinterpret_cast<float2*>(&acc[j][3]);
            float4 v0, v1;
            v0.x = fmaxf(p0.x + b0.x, 0.f);
            v0.y = fmaxf(p0.y + b0.y, 0.f);
            v0.z = fmaxf(p1.x + b0.z, 0.f);
            v0.w = fmaxf(p1.y + b0.w, 0.f);
            v1.x = fmaxf(p2.x + b1.x, 0.f);
            v1.y = fmaxf(p2.y + b1.y, 0.f);
            v1.z = fmaxf(p3.x + b1.z, 0.f);
            v1.w = fmaxf(p3.y + b1.w, 0.f);
            float* op = &g_feat[((size_t)n * 2500 + s) * 512 + ko0];
            *reinterpret_cast<float4*>(op + 4 * lane) = v0;
            *reinterpret_cast<float4*>(op + 128 + 4 * lane) = v1;
        }
    }
}

// ---------------- 1x1 heads (loc 36 + score 18) ----------------
__device__ __forceinline__ void write_head(float* out, int m, int c, float acc,
                                           const float* __restrict__ loc_b,
                                           const float* __restrict__ score_b) {
    int n = m / 2500, pos = m % 2500;
    if (c < 36) {
        int a = c >> 2, j = c & 3;
        out[(size_t)OFF_LOCS + ((size_t)n * NA + (size_t)pos * 9 + a) * 4 + j] = acc + loc_b[c];
    } else {
        int cc = c - 36;
        int a = cc >> 1, j = cc & 1;
        out[(size_t)OFF_SCORES + ((size_t)n * NA + (size_t)pos * 9 + a) * 2 + j] = acc + score_b[cc];
    }
}

__global__ void __launch_bounds__(256) heads_kernel(const float* __restrict__ loc_b,
                                                    const float* __restrict__ score_b,
                                                    float* out) {
    __shared__ float sf[16][512];
    int m0 = blockIdx.x * 16;
    int tid = threadIdx.x;
    for (int t = tid; t < 16 * 512; t += 256)
        sf[t >> 9][t & 511] = g_feat[((size_t)m0 << 9) + t];
    __syncthreads();
    int c = tid & 63;
    int mi = tid >> 6;
    if (c < 54) {
        float a0 = 0.f, a1 = 0.f, a2 = 0.f, a3 = 0.f;
#pragma unroll 4
        for (int k = 0; k < 512; k++) {
            float w = g_hwT[(size_t)k * 54 + c];
            a0 += sf[mi + 0][k] * w;
            a1 += sf[mi + 4][k] * w;
            a2 += sf[mi + 8][k] * w;
            a3 += sf[mi + 12][k] * w;
        }
        write_head(out, m0 + mi + 0, c, a0, loc_b, score_b);
        write_head(out, m0 + mi + 4, c, a1, loc_b, score_b);
        write_head(out, m0 + mi + 8, c, a2, loc_b, score_b);
        write_head(out, m0 + mi + 12, c, a3, loc_b, score_b);
    }
}

// ---------------- decode ----------------
__global__ void decode_kernel(float* out, const int* __restrict__ imh,
                              const int* __restrict__ imw) {
    int t = blockIdx.x * blockDim.x + threadIdx.x;
    if (t >= NBATCH * NA) return;
    int b = t / NA, i = t % NA;
    int pos = i / 9, a = i % 9;
    int y = pos / 50, x = pos % 50;

    int ri = a / 3, si = a % 3;
    double rr = (ri == 0) ? 0.5 : ((ri == 1) ? 1.0 : 2.0);
    double ss = (si == 0) ? 8.0 : ((si == 1) ? 16.0 : 32.0);
    double hh = 16.0 * ss * sqrt(rr);
    double wwd = 16.0 * ss * sqrt(1.0 / rr);
    float b0 = (float)(8.0 - wwd * 0.5);
    float b1 = (float)(8.0 - hh * 0.5);
    float b2 = (float)(8.0 + wwd * 0.5);
    float b3 = (float)(8.0 + hh * 0.5);
    float sx = (float)(x * 16), sy = (float)(y * 16);
    float ax1 = sx + b0, ay1 = sy + b1, ax2 = sx + b2, ay2 = sy + b3;

    if (b == 0) {
        float* ap = &out[(size_t)OFF_ANCH + (size_t)i * 4];
        ap[0] = ax1; ap[1] = ay1; ap[2] = ax2; ap[3] = ay2;
    }

    const float* lp = &out[(size_t)OFF_LOCS + ((size_t)b * NA + i) * 4];
    float l0 = lp[0], l1 = lp[1], l2 = lp[2], l3 = lp[3];
    const float* spt = &out[(size_t)OFF_SCORES + ((size_t)b * NA + i) * 2];
    float s0 = spt[0], s1 = spt[1];

    float aw = ax2 - ax1, ah = ay2 - ay1;
    float acx = ax1 + 0.5f * aw, acy = ay1 + 0.5f * ah;
    float cx = l0 * aw + acx, cy = l1 * ah + acy;
    float bw = expf(l2) * aw, bh = expf(l3) * ah;

    float Wf = (float)imw[0], Hf = (float)imh[0];
    float x1 = fminf(fmaxf(cx - 0.5f * bw, 0.f), Wf);
    float y1 = fminf(fmaxf(cy - 0.5f * bh, 0.f), Hf);
    float x2 = fminf(fmaxf(cx + 0.5f * bw, 0.f), Wf);
    float y2 = fminf(fmaxf(cy + 0.5f * bh, 0.f), Hf);

    bool valid = (x2 - x1 + 1.f >= 16.f) && (y2 - y1 + 1.f >= 16.f);

    float mx = fmaxf(s0, s1);
    float e0 = expf(s0 - mx), e1 = expf(s1 - mx);
    float fg = e1 / (e0 + e1);

    float* bp = &g_boxes[((size_t)b * NA + i) * 4];
    bp[0] = x1; bp[1] = y1; bp[2] = x2; bp[3] = y2;

    // 32-bit key: [2b batch][30b]. For fg in [0,1], ~flip(fg) always has
    // bits31:30 == 01, so the low 30 bits preserve full ordering.
    // invalid (-inf) -> low30 = 0x3FFFFFFF (> any valid low30, sorts last).
    unsigned low30;
    if (valid) {
        unsigned u = __float_as_uint(fg);
        unsigned flip = (u & 0x80000000u) ? ~u : (u | 0x80000000u);
        low30 = (~flip) & 0x3FFFFFFFu;
    } else {
        low30 = 0x3FFFFFFFu;
    }
    g_keys32[(size_t)b * NA + i] = ((unsigned)b << 30) | low30;
    g_vals[(size_t)b * NA + i] = i;
}

// ---------------- gather top-3000 ----------------
__global__ void gather_kernel() {
    int t = blockIdx.x * blockDim.x + threadIdx.x;
    if (t >= NBATCH * NPRE) return;
    int b = t / NPRE, r = t % NPRE;
    unsigned key = g_keysOut32[(size_t)b * NA + r];
    int i = g_valsOut[(size_t)b * NA + r];
    float4 box = reinterpret_cast<const float4*>(g_boxes)[(size_t)b * NA + i];
    reinterpret_cast<float4*>(g_top)[(size_t)b * NPRE + r] = box;
    g_topValid[(size_t)b * NPRE + r] = ((key & 0x3FFFFFFFu) != 0x3FFFFFFFu) ? 1 : 0;
}

// ---------------- IoU bitmask matrix (division-free) ----------------
__global__ void __launch_bounds__(128) nms_mask_kernel() {
    __shared__ float4 sb[NPRE];
    int b = blockIdx.y;
    for (int t = threadIdx.x; t < NPRE; t += 128)
        sb[t] = reinterpret_cast<const float4*>(g_top)[(size_t)b * NPRE + t];
    __syncthreads();
    int i = blockIdx.x * 128 + threadIdx.x;
    if (i >= NPRE) return;
    float4 bi = sb[i];
    float ai = (bi.z - bi.x) * (bi.w - bi.y);
    unsigned* rowp = &g_nmsMask[((size_t)b * NPRE + i) * NWORDS];
    int jw0 = i >> 5;
    for (int jw = 0; jw < NWORDS; jw++) {
        unsigned bits = 0;
        if (jw >= jw0) {
            int jbase = jw * 32;
#pragma unroll 4
            for (int k = 0; k < 32; k++) {
                int j = jbase + k;
                if (j > i && j < NPRE) {
                    float4 bj = sb[j];
                    float iw = fmaxf(fminf(bi.z, bj.z) - fmaxf(bi.x, bj.x), 0.f);
                    float ih = fmaxf(fminf(bi.w, bj.w) - fmaxf(bi.y, bj.y), 0.f);
                    float inter = iw * ih;
                    float aj = (bj.z - bj.x) * (bj.w - bj.y);
                    if (inter > 0.7f * (ai + aj - inter + 1e-9f)) bits |= 1u << k;
                }
            }
        }
        rowp[jw] = bits;
    }
}

// ---------------- greedy scan: ffs skip over suppressed ----------------
__global__ void __launch_bounds__(32) nms_scan_kernel(float* out) {
    __shared__ unsigned sup[96];
    __shared__ unsigned vb[96];
    int b = blockIdx.x;
    int lane = threadIdx.x;

    for (int t = lane; t < NPOST * 4; t += 32)
        out[(size_t)OFF_ROIS + (size_t)b * NPOST * 4 + t] = 0.f;

#pragma unroll
    for (int q = 0; q < 3; q++) {
        int w = lane + 32 * q;
        sup[w] = 0;
        unsigned v = 0;
        if (w < NWORDS) {
            for (int k = 0; k < 32; k++) {
                int j = w * 32 + k;
                if (j < NPRE && g_topValid[(size_t)b * NPRE + j]) v |= 1u << k;
            }
        }
        vb[w] = v;
    }
    __syncwarp();

    const unsigned* maskBase = &g_nmsMask[(size_t)b * NPRE * NWORDS];
    int cnt = 0;
    int i = 0;
    while (cnt < NPOST) {
        int w = i >> 5;
        if (w >= NWORDS) break;
        unsigned live = (vb[w] & ~sup[w]) & (0xFFFFFFFFu << (i & 31));
        while (live == 0) {
            if (++w >= NWORDS) { w = -1; break; }
            live = vb[w] & ~sup[w];
        }
        if (w < 0) break;
        i = w * 32 + (__ffs(live) - 1);

        if (lane < 4)
            out[(size_t)OFF_ROIS + ((size_t)b * NPOST + cnt) * 4 + lane] =
                g_top[((size_t)b * NPRE + i) * 4 + lane];
        cnt++;

        const unsigned* row = maskBase + (size_t)i * NWORDS;
#pragma unroll
        for (int q = 0; q < 3; q++) {
            int ww = lane + 32 * q;
            if (ww < NWORDS) sup[ww] |= row[ww];
        }
        __syncwarp();
        i++;
    }
}

// ---------------- roi indices ----------------
__global__ void ridx_kernel(float* out) {
    int t = blockIdx.x * blockDim.x + threadIdx.x;
    if (t < NBATCH * NPOST) out[(size_t)OFF_RIDX + t] = (float)(t / NPOST);
}

// ---------------- launch ----------------
extern "C" void kernel_launch(void* const* d_in, const int* in_sizes, int n_in,
                              void* d_out, int out_size) {
    const float* x = (const float*)d_in[0];
    const float* conv1_w = (const float*)d_in[1];
    const float* conv1_b = (const float*)d_in[2];
    const float* loc_w = (const float*)d_in[3];
    const float* loc_b = (const float*)d_in[4];
    const float* score_w = (const float*)d_in[5];
    const float* score_b = (const float*)d_in[6];
    const int* img_h = (const int*)d_in[7];
    const int* img_w = (const int*)d_in[8];
    float* out = (float*)d_out;

    wtrans_kernel<<<(512 * 9 * 512 + 255) / 256, 256>>>(conv1_w);   // 1
    hwtrans_kernel<<<(512 * 54 + 255) / 256, 256>>>(loc_w, score_w); // 2
    dummy_k<<<1, 32>>>();                                            // 3
    dummy_k<<<1, 32>>>();                                            // 4
    dummy_k<<<1, 32>>>();                                            // 5

    cudaFuncSetAttribute(conv3x3_v4, cudaFuncAttributeMaxDynamicSharedMemorySize,
                         CONV_SMEM);
    conv3x3_v4<<<dim3(35, 2, NBATCH), 256, CONV_SMEM>>>(x, conv1_b); // 6 (profiled)

    heads_kernel<<<625, 256>>>(loc_b, score_b, out);

    decode_kernel<<<(NBATCH * NA + 255) / 256, 256>>>(out, img_h, img_w);

    // single full-device stable radix sort over 32-bit [2b batch | 30b score]
    void *pKeys, *pKeysOut, *pVals, *pValsOut, *pTemp;
    cudaGetSymbolAddress(&pKeys, g_keys32);
    cudaGetSymbolAddress(&pKeysOut, g_keysOut32);
    cudaGetSymbolAddress(&pVals, g_vals);
    cudaGetSymbolAddress(&pValsOut, g_valsOut);
    cudaGetSymbolAddress(&pTemp, g_cubTemp);

    size_t temp_bytes = 0;
    cub::DeviceRadixSort::SortPairs(
        nullptr, temp_bytes,
        (const unsigned*)pKeys, (unsigned*)pKeysOut,
        (const int*)pVals, (int*)pValsOut, NBATCH * NA, 0, 32, (cudaStream_t)0);
    if (temp_bytes <= (size_t)(16 << 20)) {
        cub::DeviceRadixSort::SortPairs(
            pTemp, temp_bytes,
            (const unsigned*)pKeys, (unsigned*)pKeysOut,
            (const int*)pVals, (int*)pValsOut, NBATCH * NA, 0, 32, (cudaStream_t)0);
    }

    gather_kernel<<<(NBATCH * NPRE + 255) / 256, 256>>>();
    nms_mask_kernel<<<dim3((NPRE + 127) / 128, NBATCH), 128>>>();
    nms_scan_kernel<<<NBATCH, 32>>>(out);
    ridx_kernel<<<(NBATCH * NPOST + 255) / 256, 256>>>(out);
}